// round 5
// baseline (speedup 1.0000x reference)
#include <cuda_runtime.h>
#include <cuda_bf16.h>
#include <math.h>
#include <stdint.h>

// ---------------- problem constants ----------------
#define N_MAXN    50000
#define NPAD      50176          // 196 * 256
#define MEM_DIM   100
#define RAW       64
#define TIN       20
#define D_MSG     292
#define KT1       400            // K per split term (392 real + 8 pad)
#define AK        800            // A row: [Ahi(400) | Alo(400)]
#define KTOT      1200           // GEMM K: [Ahi*Bhi | Ahi*Blo | Alo*Bhi]
#define JPAD      512            // interleaved: j' = channel*4 + group

// ---------------- scratch ----------------
__device__ __nv_bfloat16 g_A[(size_t)NPAD * AK];    // ~80 MB
__device__ __nv_bfloat16 g_B[(size_t)JPAD * KTOT];  // ~1.2 MB
__device__ float         g_mem[(size_t)NPAD * MEM_DIM];

__device__ __forceinline__ uint32_t smem_u32(const void* p) {
    uint32_t a;
    asm("{ .reg .u64 t; cvta.to.shared.u64 t, %1; cvt.u32.u64 %0, t; }" : "=r"(a) : "l"(p));
    return a;
}
__device__ __forceinline__ void cp_async16(uint32_t dst, const void* src) {
    asm volatile("cp.async.cg.shared.global [%0], [%1], 16;" :: "r"(dst), "l"(src));
}
__device__ __forceinline__ void cp_commit() {
    asm volatile("cp.async.commit_group;" ::: "memory");
}
__device__ __forceinline__ void cp_wait1() {
    asm volatile("cp.async.wait_group 1;" ::: "memory");
}
__device__ __forceinline__ void ldmx4(uint32_t* r, uint32_t addr) {
    asm volatile("ldmatrix.sync.aligned.m8n8.x4.shared.b16 {%0,%1,%2,%3}, [%4];"
        : "=r"(r[0]), "=r"(r[1]), "=r"(r[2]), "=r"(r[3]) : "r"(addr));
}
__device__ __forceinline__ void mma16816(float* d, const uint32_t* a, const uint32_t* b) {
    asm volatile(
        "mma.sync.aligned.m16n8k16.row.col.f32.bf16.bf16.f32 "
        "{%0,%1,%2,%3}, {%4,%5,%6,%7}, {%8,%9}, {%0,%1,%2,%3};"
        : "+f"(d[0]), "+f"(d[1]), "+f"(d[2]), "+f"(d[3])
        : "r"(a[0]), "r"(a[1]), "r"(a[2]), "r"(a[3]), "r"(b[0]), "r"(b[1]));
}
__device__ __forceinline__ void bsplit(float x, __nv_bfloat16& h, __nv_bfloat16& l) {
    h = __float2bfloat16(x);
    l = __float2bfloat16(x - __bfloat162float(h));
}

// ---------------------------------------------------------------------------
// Kernel 0: pack GRU weights -> g_B [512][1200] bf16, terms [Bhi|Blo|Bhi].
// Row j' = c*4 + g  (c = channel 0..127, g = group: 0=r 1=z 2=gi_n 3=gh_n)
// ---------------------------------------------------------------------------
__global__ void buildB(const float* __restrict__ wih, const float* __restrict__ whh) {
    int idx = blockIdx.x * blockDim.x + threadIdx.x;
    if (idx >= JPAD * KTOT) return;
    int j = idx / KTOT, k = idx % KTOT;
    int c = j >> 2, g = j & 3;
    int t = k / KT1, kk = k % KT1;
    float v = 0.0f;
    if (c < 100) {
        if (kk < D_MSG) {
            if (g == 0) v = wih[c * D_MSG + kk];
            else if (g == 1) v = wih[(100 + c) * D_MSG + kk];
            else if (g == 2) v = wih[(200 + c) * D_MSG + kk];
        } else if (kk < D_MSG + MEM_DIM) {
            int m = kk - D_MSG;
            if (g == 0) v = whh[c * MEM_DIM + m];
            else if (g == 1) v = whh[(100 + c) * MEM_DIM + m];
            else if (g == 3) v = whh[(200 + c) * MEM_DIM + m];
        }
    }
    __nv_bfloat16 h, l;
    bsplit(v, h, l);
    g_B[idx] = (t == 1) ? l : h;
}

// ---------------------------------------------------------------------------
// Kernel 1: per-node msg MLP + layernorms -> g_A row [hi(400)|lo(400)] + g_mem.
// ---------------------------------------------------------------------------
__global__ __launch_bounds__(64) void phase1(
    const int* __restrict__ n_id,
    const float* __restrict__ memory,
    const float* __restrict__ msgs,
    const float* __restrict__ w1, const float* __restrict__ b1,
    const float* __restrict__ w2, const float* __restrict__ b2,
    const float* __restrict__ lg, const float* __restrict__ lb,
    const float* __restrict__ lng, const float* __restrict__ lnb,
    int N)
{
    __shared__ float sm[RAW * TIN];
    __shared__ float sv[D_MSG];
    __shared__ float red[4];
    __shared__ float s_mu, s_rs;

    int i = blockIdx.x;
    int tid = threadIdx.x;
    size_t base = (size_t)i * AK;

    if (i >= N) {  // zero pad rows
        uint4 z = make_uint4(0, 0, 0, 0);
        uint4* dst = (uint4*)(g_A + base);
        for (int k = tid; k < AK / 8; k += 64) dst[k] = z;
        return;
    }
    int row = n_id[i];

    const float4* src4 = (const float4*)(msgs + (size_t)row * (RAW * TIN));
    float4* sm4 = (float4*)sm;
#pragma unroll
    for (int t = tid; t < RAW * TIN / 4; t += 64) sm4[t] = src4[t];
    const float* memrow = memory + (size_t)row * MEM_DIM;
    for (int c = tid; c < MEM_DIM; c += 64) sv[c] = memrow[c];
    __syncthreads();

    {
        const float* mr = sm + tid * TIN;
        float h[10];
#pragma unroll
        for (int j = 0; j < 10; j++) {
            float s = __ldg(b1 + j);
#pragma unroll
            for (int t = 0; t < TIN; t++) s += mr[t] * __ldg(w1 + j * TIN + t);
            h[j] = 0.5f * s * (1.0f + erff(s * 0.7071067811865476f));
        }
        float y[3];
#pragma unroll
        for (int o = 0; o < 3; o++) {
            float s = __ldg(b2 + o);
#pragma unroll
            for (int j = 0; j < 10; j++) s += h[j] * __ldg(w2 + o * 10 + j);
            y[o] = s;
        }
        float mu = (y[0] + y[1] + y[2]) * (1.0f / 3.0f);
        float d0 = y[0] - mu, d1 = y[1] - mu, d2 = y[2] - mu;
        float var = (d0 * d0 + d1 * d1 + d2 * d2) * (1.0f / 3.0f);
        float rs = rsqrtf(var + 1e-5f);
        sv[MEM_DIM + 3 * tid + 0] = d0 * rs * __ldg(lg + 0) + __ldg(lb + 0);
        sv[MEM_DIM + 3 * tid + 1] = d1 * rs * __ldg(lg + 1) + __ldg(lb + 1);
        sv[MEM_DIM + 3 * tid + 2] = d2 * rs * __ldg(lg + 2) + __ldg(lb + 2);
    }
    __syncthreads();

    float s1 = 0.0f, s2 = 0.0f;
    for (int k = tid; k < D_MSG; k += 64) { float v = sv[k]; s1 += v; s2 += v * v; }
#pragma unroll
    for (int o = 16; o > 0; o >>= 1) {
        s1 += __shfl_down_sync(0xFFFFFFFFu, s1, o);
        s2 += __shfl_down_sync(0xFFFFFFFFu, s2, o);
    }
    if ((tid & 31) == 0) { red[tid >> 5] = s1; red[2 + (tid >> 5)] = s2; }
    __syncthreads();
    if (tid == 0) {
        float t1 = red[0] + red[1];
        float t2 = red[2] + red[3];
        float mu = t1 * (1.0f / 292.0f);
        float var = t2 * (1.0f / 292.0f) - mu * mu;
        s_mu = mu;
        s_rs = rsqrtf(var + 1e-5f);
    }
    __syncthreads();

    float mu = s_mu, rs = s_rs;
    for (int k = tid; k < D_MSG; k += 64) {
        float v = (sv[k] - mu) * rs * __ldg(lng + k) + __ldg(lnb + k);
        __nv_bfloat16 h, l; bsplit(v, h, l);
        g_A[base + k] = h; g_A[base + KT1 + k] = l;
    }
    for (int c = tid; c < MEM_DIM; c += 64) {
        float v = sv[c];
        __nv_bfloat16 h, l; bsplit(v, h, l);
        g_A[base + D_MSG + c] = h; g_A[base + KT1 + D_MSG + c] = l;
        g_mem[(size_t)i * MEM_DIM + c] = v;
    }
    if (tid < 8) {
        __nv_bfloat16 z = __float2bfloat16(0.0f);
        g_A[base + 392 + tid] = z;
        g_A[base + KT1 + 392 + tid] = z;
    }
}

// ---------------------------------------------------------------------------
// Kernel 2: fused bf16 HMMA GEMM + GRU epilogue.
// BM=256 BN=128 BK=48, 512 threads, 16 warps (4x4, warp tile 64x32),
// 3-stage cp.async pipeline. Each CTA owns 32 channels x 4 gate groups
// (interleaved B rows) -> computes gates locally, writes out directly.
// ---------------------------------------------------------------------------
#define BM 256
#define BN 128
#define BK 48
#define LDS 56
#define NKT (KTOT / BK)        // 25
#define A_H (BM * LDS)         // halves per A stage = 14336
#define B_H (BN * LDS)         // halves per B stage = 7168
#define STG_H (A_H + B_H)      // 21504 halves = 43008 B
#define CS_STRIDE 132
#define SMEM_GEMM (BM * CS_STRIDE * 4)   // 135168 (Cs) > 3*43008 (staging)

__global__ __launch_bounds__(512, 1) void gemm5(float* __restrict__ out, int N) {
    extern __shared__ __align__(16) uint16_t smx[];

    int tid = threadIdx.x;
    int lane = tid & 31, wid = tid >> 5;
    int wm = wid & 3, wn = wid >> 2;       // 4 x 4 warp grid
    int row0 = blockIdx.y * BM;
    int colblk = blockIdx.x;               // channels [colblk*32, +32)
    int col0 = colblk * BN;

    const uint16_t* gA = (const uint16_t*)g_A;
    const uint16_t* gB = (const uint16_t*)g_B;

    float acc[4][4][4];
#pragma unroll
    for (int mf = 0; mf < 4; mf++)
#pragma unroll
        for (int nf = 0; nf < 4; nf++)
#pragma unroll
            for (int q = 0; q < 4; q++) acc[mf][nf][q] = 0.0f;

    // loader: A = 256 rows x 6 chunks (1536), B = 128 x 6 (768); 2304 chunks.
    auto load_stage = [&](int stage, int k0) {
        uint16_t* As = smx + stage * STG_H;
        uint16_t* Bs = As + A_H;
#pragma unroll
        for (int q = 0; q < 5; q++) {
            int id = tid + q * 512;
            if (id < 1536) {
                int r = id / 6, c = id % 6;
                int kk = k0 + c * 8;
                int ak = (kk < KT1) ? kk : kk - KT1;
                cp_async16(smem_u32(&As[r * LDS + c * 8]),
                           gA + (size_t)(row0 + r) * AK + ak);
            } else if (id < 2304) {
                int id2 = id - 1536;
                int r = id2 / 6, c = id2 % 6;
                cp_async16(smem_u32(&Bs[r * LDS + c * 8]),
                           gB + (size_t)(col0 + r) * KTOT + k0 + c * 8);
            }
        }
        cp_commit();
    };

    load_stage(0, 0);
    load_stage(1, BK);

    for (int kt = 0; kt < NKT; kt++) {
        int buf = kt % 3;
        cp_wait1();
        __syncthreads();
        if (kt + 2 < NKT) load_stage((kt + 2) % 3, (kt + 2) * BK);

        uint16_t* As = smx + buf * STG_H;
        uint16_t* Bs = As + A_H;
#pragma unroll
        for (int ks = 0; ks < 3; ks++) {
            int k0 = ks * 16;
            uint32_t a[4][4], b[4][2];
#pragma unroll
            for (int mf = 0; mf < 4; mf++) {
                int r = wm * 64 + mf * 16 + (lane & 15);
                int c = k0 + (lane >> 4) * 8;
                ldmx4(a[mf], smem_u32(&As[r * LDS + c]));
            }
#pragma unroll
            for (int nb = 0; nb < 2; nb++) {
                int r = wn * 32 + nb * 16 + (lane & 7) + ((lane >> 4) << 3);
                int c = k0 + ((lane >> 3) & 1) * 8;
                uint32_t bb[4];
                ldmx4(bb, smem_u32(&Bs[r * LDS + c]));
                b[2 * nb][0] = bb[0]; b[2 * nb][1] = bb[1];
                b[2 * nb + 1][0] = bb[2]; b[2 * nb + 1][1] = bb[3];
            }
#pragma unroll
            for (int mf = 0; mf < 4; mf++)
#pragma unroll
                for (int nf = 0; nf < 4; nf++)
                    mma16816(acc[mf][nf], a[mf], b[nf]);
        }
        __syncthreads();
    }

    // stage accumulators to smem C tile [256][128] (stride 132)
    __syncthreads();
    float* Cs = (float*)smx;
#pragma unroll
    for (int mf = 0; mf < 4; mf++) {
        int r = wm * 64 + mf * 16 + (lane >> 2);
#pragma unroll
        for (int nf = 0; nf < 4; nf++) {
            int c = wn * 32 + nf * 8 + (lane & 3) * 2;
            Cs[r * CS_STRIDE + c] = acc[mf][nf][0];
            Cs[r * CS_STRIDE + c + 1] = acc[mf][nf][1];
            Cs[(r + 8) * CS_STRIDE + c] = acc[mf][nf][2];
            Cs[(r + 8) * CS_STRIDE + c + 1] = acc[mf][nf][3];
        }
    }
    __syncthreads();

    // fused GRU epilogue: 256 rows x 32 channels = 8192 outputs
#pragma unroll
    for (int q = 0; q < 16; q++) {
        int idx = tid + q * 512;
        int r = idx >> 5, cc = idx & 31;
        int i = row0 + r;
        int c = colblk * 32 + cc;
        if (i < N && c < MEM_DIM) {
            const float* g4 = Cs + r * CS_STRIDE + cc * 4;
            float rr = 1.0f / (1.0f + expf(-g4[0]));
            float zz = 1.0f / (1.0f + expf(-g4[1]));
            float nn = tanhf(fmaf(rr, g4[3], g4[2]));
            float m = g_mem[(size_t)i * MEM_DIM + c];
            out[(size_t)i * MEM_DIM + c] = (1.0f - zz) * nn + zz * m;
        }
    }
}

// ---------------------------------------------------------------------------
extern "C" void kernel_launch(void* const* d_in, const int* in_sizes, int n_in,
                              void* d_out, int out_size) {
    const int*   n_id   = (const int*)d_in[0];
    const float* memory = (const float*)d_in[1];
    const float* msgs   = (const float*)d_in[2];
    const float* w1     = (const float*)d_in[3];
    const float* b1     = (const float*)d_in[4];
    const float* w2     = (const float*)d_in[5];
    const float* b2     = (const float*)d_in[6];
    const float* lg     = (const float*)d_in[7];
    const float* lb     = (const float*)d_in[8];
    const float* lng    = (const float*)d_in[9];
    const float* lnb    = (const float*)d_in[10];
    const float* wih    = (const float*)d_in[11];
    const float* whh    = (const float*)d_in[12];
    float* out = (float*)d_out;

    int N = in_sizes[0];
    if (N > N_MAXN) N = N_MAXN;

    cudaFuncSetAttribute(gemm5, cudaFuncAttributeMaxDynamicSharedMemorySize, SMEM_GEMM);

    buildB<<<(JPAD * KTOT + 255) / 256, 256>>>(wih, whh);
    phase1<<<NPAD, 64>>>(n_id, memory, msgs, w1, b1, w2, b2, lg, lb, lng, lnb, N);
    dim3 grid(JPAD / BN, NPAD / BM);   // col-block fast -> A shared in L2
    gemm5<<<grid, 512, SMEM_GEMM>>>(out, N);
}

// round 6
// speedup vs baseline: 1.0837x; 1.0837x over previous
#include <cuda_runtime.h>
#include <cuda_bf16.h>
#include <math.h>
#include <stdint.h>

// ---------------- problem constants ----------------
#define N_MAXN    50000
#define NPAD      50048          // 391 * 128
#define MEM_DIM   100
#define RAW       64
#define TIN       20
#define D_MSG     292
#define KT1       400            // K per split term (392 real + 8 pad)
#define AK        800            // A row: [Ahi(400) | Alo(400)]
#define KTOT      1200           // GEMM K: [Ahi*Bhi | Ahi*Blo | Alo*Bhi]
#define JPAD      512            // interleaved: j' = channel*4 + group

// ---------------- scratch ----------------
__device__ __nv_bfloat16 g_A[(size_t)NPAD * AK];    // ~80 MB
__device__ __nv_bfloat16 g_B[(size_t)JPAD * KTOT];  // ~1.2 MB
__device__ float         g_mem[(size_t)NPAD * MEM_DIM];

__device__ __forceinline__ uint32_t smem_u32(const void* p) {
    uint32_t a;
    asm("{ .reg .u64 t; cvta.to.shared.u64 t, %1; cvt.u32.u64 %0, t; }" : "=r"(a) : "l"(p));
    return a;
}
__device__ __forceinline__ void cp_async16(uint32_t dst, const void* src) {
    asm volatile("cp.async.cg.shared.global [%0], [%1], 16;" :: "r"(dst), "l"(src));
}
__device__ __forceinline__ void cp_commit() {
    asm volatile("cp.async.commit_group;" ::: "memory");
}
__device__ __forceinline__ void cp_wait_all() {
    asm volatile("cp.async.wait_group 0;" ::: "memory");
}
__device__ __forceinline__ void ldmx4(uint32_t* r, uint32_t addr) {
    asm volatile("ldmatrix.sync.aligned.m8n8.x4.shared.b16 {%0,%1,%2,%3}, [%4];"
        : "=r"(r[0]), "=r"(r[1]), "=r"(r[2]), "=r"(r[3]) : "r"(addr));
}
__device__ __forceinline__ void mma16816(float* d, const uint32_t* a, const uint32_t* b) {
    asm volatile(
        "mma.sync.aligned.m16n8k16.row.col.f32.bf16.bf16.f32 "
        "{%0,%1,%2,%3}, {%4,%5,%6,%7}, {%8,%9}, {%0,%1,%2,%3};"
        : "+f"(d[0]), "+f"(d[1]), "+f"(d[2]), "+f"(d[3])
        : "r"(a[0]), "r"(a[1]), "r"(a[2]), "r"(a[3]), "r"(b[0]), "r"(b[1]));
}
__device__ __forceinline__ void bsplit(float x, __nv_bfloat16& h, __nv_bfloat16& l) {
    h = __float2bfloat16(x);
    l = __float2bfloat16(x - __bfloat162float(h));
}

// ---------------------------------------------------------------------------
// Kernel 0: pack GRU weights -> g_B [512][1200] bf16, terms [Bhi|Blo|Bhi].
// Row j' = c*4 + g  (c = channel 0..127, g: 0=r 1=z 2=gi_n 3=gh_n)
// ---------------------------------------------------------------------------
__global__ void buildB(const float* __restrict__ wih, const float* __restrict__ whh) {
    int idx = blockIdx.x * blockDim.x + threadIdx.x;
    if (idx >= JPAD * KTOT) return;
    int j = idx / KTOT, k = idx % KTOT;
    int c = j >> 2, g = j & 3;
    int t = k / KT1, kk = k % KT1;
    float v = 0.0f;
    if (c < 100) {
        if (kk < D_MSG) {
            if (g == 0) v = wih[c * D_MSG + kk];
            else if (g == 1) v = wih[(100 + c) * D_MSG + kk];
            else if (g == 2) v = wih[(200 + c) * D_MSG + kk];
        } else if (kk < D_MSG + MEM_DIM) {
            int m = kk - D_MSG;
            if (g == 0) v = whh[c * MEM_DIM + m];
            else if (g == 1) v = whh[(100 + c) * MEM_DIM + m];
            else if (g == 3) v = whh[(200 + c) * MEM_DIM + m];
        }
    }
    __nv_bfloat16 h, l;
    bsplit(v, h, l);
    g_B[idx] = (t == 1) ? l : h;
}

// ---------------------------------------------------------------------------
// Kernel 1: per-node msg MLP + layernorms -> g_A row [hi(400)|lo(400)] + g_mem.
// ---------------------------------------------------------------------------
__global__ __launch_bounds__(64) void phase1(
    const int* __restrict__ n_id,
    const float* __restrict__ memory,
    const float* __restrict__ msgs,
    const float* __restrict__ w1, const float* __restrict__ b1,
    const float* __restrict__ w2, const float* __restrict__ b2,
    const float* __restrict__ lg, const float* __restrict__ lb,
    const float* __restrict__ lng, const float* __restrict__ lnb,
    int N)
{
    __shared__ float sm[RAW * TIN];
    __shared__ float sv[D_MSG];
    __shared__ float red[4];
    __shared__ float s_mu, s_rs;

    int i = blockIdx.x;
    int tid = threadIdx.x;
    size_t base = (size_t)i * AK;

    if (i >= N) {  // zero pad rows
        uint4 z = make_uint4(0, 0, 0, 0);
        uint4* dst = (uint4*)(g_A + base);
        for (int k = tid; k < AK / 8; k += 64) dst[k] = z;
        return;
    }
    int row = n_id[i];

    const float4* src4 = (const float4*)(msgs + (size_t)row * (RAW * TIN));
    float4* sm4 = (float4*)sm;
#pragma unroll
    for (int t = tid; t < RAW * TIN / 4; t += 64) sm4[t] = src4[t];
    const float* memrow = memory + (size_t)row * MEM_DIM;
    for (int c = tid; c < MEM_DIM; c += 64) sv[c] = memrow[c];
    __syncthreads();

    {
        const float* mr = sm + tid * TIN;
        float h[10];
#pragma unroll
        for (int j = 0; j < 10; j++) {
            float s = __ldg(b1 + j);
#pragma unroll
            for (int t = 0; t < TIN; t++) s += mr[t] * __ldg(w1 + j * TIN + t);
            h[j] = 0.5f * s * (1.0f + erff(s * 0.7071067811865476f));
        }
        float y[3];
#pragma unroll
        for (int o = 0; o < 3; o++) {
            float s = __ldg(b2 + o);
#pragma unroll
            for (int j = 0; j < 10; j++) s += h[j] * __ldg(w2 + o * 10 + j);
            y[o] = s;
        }
        float mu = (y[0] + y[1] + y[2]) * (1.0f / 3.0f);
        float d0 = y[0] - mu, d1 = y[1] - mu, d2 = y[2] - mu;
        float var = (d0 * d0 + d1 * d1 + d2 * d2) * (1.0f / 3.0f);
        float rs = rsqrtf(var + 1e-5f);
        sv[MEM_DIM + 3 * tid + 0] = d0 * rs * __ldg(lg + 0) + __ldg(lb + 0);
        sv[MEM_DIM + 3 * tid + 1] = d1 * rs * __ldg(lg + 1) + __ldg(lb + 1);
        sv[MEM_DIM + 3 * tid + 2] = d2 * rs * __ldg(lg + 2) + __ldg(lb + 2);
    }
    __syncthreads();

    float s1 = 0.0f, s2 = 0.0f;
    for (int k = tid; k < D_MSG; k += 64) { float v = sv[k]; s1 += v; s2 += v * v; }
#pragma unroll
    for (int o = 16; o > 0; o >>= 1) {
        s1 += __shfl_down_sync(0xFFFFFFFFu, s1, o);
        s2 += __shfl_down_sync(0xFFFFFFFFu, s2, o);
    }
    if ((tid & 31) == 0) { red[tid >> 5] = s1; red[2 + (tid >> 5)] = s2; }
    __syncthreads();
    if (tid == 0) {
        float t1 = red[0] + red[1];
        float t2 = red[2] + red[3];
        float mu = t1 * (1.0f / 292.0f);
        float var = t2 * (1.0f / 292.0f) - mu * mu;
        s_mu = mu;
        s_rs = rsqrtf(var + 1e-5f);
    }
    __syncthreads();

    float mu = s_mu, rs = s_rs;
    for (int k = tid; k < D_MSG; k += 64) {
        float v = (sv[k] - mu) * rs * __ldg(lng + k) + __ldg(lnb + k);
        __nv_bfloat16 h, l; bsplit(v, h, l);
        g_A[base + k] = h; g_A[base + KT1 + k] = l;
    }
    for (int c = tid; c < MEM_DIM; c += 64) {
        float v = sv[c];
        __nv_bfloat16 h, l; bsplit(v, h, l);
        g_A[base + D_MSG + c] = h; g_A[base + KT1 + D_MSG + c] = l;
        g_mem[(size_t)i * MEM_DIM + c] = v;
    }
    if (tid < 8) {
        __nv_bfloat16 z = __float2bfloat16(0.0f);
        g_A[base + 392 + tid] = z;
        g_A[base + KT1 + 392 + tid] = z;
    }
}

// ---------------------------------------------------------------------------
// Kernel 2: bf16 HMMA GEMM + register-fused GRU epilogue.
// BM=128 BN=128 BK=48, 256 threads, 8 warps (2x4, warp tile 64x32),
// cp.async double buffer (R4 config). B rows interleaved (channel*4+group):
// shfl_xor(1) pairs (r,z) with (gin,ghn) of the same channel -> write out.
// ---------------------------------------------------------------------------
#define BM 128
#define BN 128
#define BK 48
#define LDS 56
#define NKT (KTOT / BK)   // 25
#define TILE_H (BM * LDS)          // halves per A/B stage
#define SMEM_GEMM (4 * TILE_H * 2) // 57344 B

__global__ __launch_bounds__(256, 2) void gemm6(float* __restrict__ out, int N) {
    extern __shared__ __align__(16) uint16_t smx[];
    uint16_t* As[2] = { smx, smx + TILE_H };
    uint16_t* Bs[2] = { smx + 2 * TILE_H, smx + 3 * TILE_H };

    int tid = threadIdx.x;
    int lane = tid & 31, wid = tid >> 5;
    int wm = wid & 1, wn = wid >> 1;            // 2 x 4 warp grid
    int row0 = blockIdx.y * BM;
    int colblk = blockIdx.x;                    // channels [colblk*32, +32)
    int col0 = colblk * BN;

    const uint16_t* gA = (const uint16_t*)g_A;
    const uint16_t* gB = (const uint16_t*)g_B;

    float acc[4][4][4];
#pragma unroll
    for (int mf = 0; mf < 4; mf++)
#pragma unroll
        for (int nf = 0; nf < 4; nf++)
#pragma unroll
            for (int q = 0; q < 4; q++) acc[mf][nf][q] = 0.0f;

#pragma unroll
    for (int q = 0; q < 3; q++) {
        int id = tid + q * 256;
        int r = id / 6, c = id % 6;
        int kk = c * 8;
        int ak = (kk < KT1) ? kk : kk - KT1;
        cp_async16(smem_u32(&As[0][r * LDS + c * 8]), gA + (size_t)(row0 + r) * AK + ak);
        cp_async16(smem_u32(&Bs[0][r * LDS + c * 8]), gB + (size_t)(col0 + r) * KTOT + kk);
    }
    cp_commit();

    for (int kt = 0; kt < NKT; kt++) {
        int buf = kt & 1;
        cp_wait_all();
        __syncthreads();
        if (kt + 1 < NKT) {
            int k0 = (kt + 1) * BK;
#pragma unroll
            for (int q = 0; q < 3; q++) {
                int id = tid + q * 256;
                int r = id / 6, c = id % 6;
                int kk = k0 + c * 8;
                int ak = (kk < KT1) ? kk : kk - KT1;
                cp_async16(smem_u32(&As[buf ^ 1][r * LDS + c * 8]),
                           gA + (size_t)(row0 + r) * AK + ak);
                cp_async16(smem_u32(&Bs[buf ^ 1][r * LDS + c * 8]),
                           gB + (size_t)(col0 + r) * KTOT + kk);
            }
            cp_commit();
        }

#pragma unroll
        for (int ks = 0; ks < 3; ks++) {
            int k0 = ks * 16;
            uint32_t a[4][4], b[4][2];
#pragma unroll
            for (int mf = 0; mf < 4; mf++) {
                int r = wm * 64 + mf * 16 + (lane & 15);
                int c = k0 + (lane >> 4) * 8;
                ldmx4(a[mf], smem_u32(&As[buf][r * LDS + c]));
            }
#pragma unroll
            for (int nb = 0; nb < 2; nb++) {
                int r = wn * 32 + nb * 16 + (lane & 7) + ((lane >> 4) << 3);
                int c = k0 + ((lane >> 3) & 1) * 8;
                uint32_t bb[4];
                ldmx4(bb, smem_u32(&Bs[buf][r * LDS + c]));
                b[2 * nb][0] = bb[0]; b[2 * nb][1] = bb[1];
                b[2 * nb + 1][0] = bb[2]; b[2 * nb + 1][1] = bb[3];
            }
#pragma unroll
            for (int mf = 0; mf < 4; mf++)
#pragma unroll
                for (int nf = 0; nf < 4; nf++)
                    mma16816(acc[mf][nf], a[mf], b[nf]);
        }
        __syncthreads();
    }

    // Register-fused GRU epilogue.
    // Thread's 2 j-cols: j = wn*32 + nf*8 + (lane&3)*2, +1  -> channel j>>2,
    // groups {0,1} (even lane) or {2,3} (odd lane); partner = lane^1.
#pragma unroll
    for (int mf = 0; mf < 4; mf++) {
        int r0i = row0 + wm * 64 + mf * 16 + (lane >> 2);
#pragma unroll
        for (int nf = 0; nf < 4; nf++) {
            float n0 = __shfl_xor_sync(0xFFFFFFFFu, acc[mf][nf][0], 1);
            float n1 = __shfl_xor_sync(0xFFFFFFFFu, acc[mf][nf][1], 1);
            float n2 = __shfl_xor_sync(0xFFFFFFFFu, acc[mf][nf][2], 1);
            float n3 = __shfl_xor_sync(0xFFFFFFFFu, acc[mf][nf][3], 1);
            if (!(lane & 1)) {
                int ch = colblk * 32 + wn * 8 + nf * 2 + ((lane & 3) >> 1);
                if (ch < MEM_DIM) {
                    if (r0i < N) {
                        float rr = 1.0f / (1.0f + expf(-acc[mf][nf][0]));
                        float zz = 1.0f / (1.0f + expf(-acc[mf][nf][1]));
                        float nn = tanhf(fmaf(rr, n1, n0));
                        float m = g_mem[(size_t)r0i * MEM_DIM + ch];
                        out[(size_t)r0i * MEM_DIM + ch] = (1.0f - zz) * nn + zz * m;
                    }
                    int r1i = r0i + 8;
                    if (r1i < N) {
                        float rr = 1.0f / (1.0f + expf(-acc[mf][nf][2]));
                        float zz = 1.0f / (1.0f + expf(-acc[mf][nf][3]));
                        float nn = tanhf(fmaf(rr, n3, n2));
                        float m = g_mem[(size_t)r1i * MEM_DIM + ch];
                        out[(size_t)r1i * MEM_DIM + ch] = (1.0f - zz) * nn + zz * m;
                    }
                }
            }
        }
    }
}

// ---------------------------------------------------------------------------
extern "C" void kernel_launch(void* const* d_in, const int* in_sizes, int n_in,
                              void* d_out, int out_size) {
    const int*   n_id   = (const int*)d_in[0];
    const float* memory = (const float*)d_in[1];
    const float* msgs   = (const float*)d_in[2];
    const float* w1     = (const float*)d_in[3];
    const float* b1     = (const float*)d_in[4];
    const float* w2     = (const float*)d_in[5];
    const float* b2     = (const float*)d_in[6];
    const float* lg     = (const float*)d_in[7];
    const float* lb     = (const float*)d_in[8];
    const float* lng    = (const float*)d_in[9];
    const float* lnb    = (const float*)d_in[10];
    const float* wih    = (const float*)d_in[11];
    const float* whh    = (const float*)d_in[12];
    float* out = (float*)d_out;

    int N = in_sizes[0];
    if (N > N_MAXN) N = N_MAXN;

    cudaFuncSetAttribute(gemm6, cudaFuncAttributeMaxDynamicSharedMemorySize, SMEM_GEMM);

    buildB<<<(JPAD * KTOT + 255) / 256, 256>>>(wih, whh);
    phase1<<<NPAD, 64>>>(n_id, memory, msgs, w1, b1, w2, b2, lg, lb, lng, lnb, N);
    dim3 grid(JPAD / BN, NPAD / BM);   // col-block fast -> A shared in L2
    gemm6<<<grid, 256, SMEM_GEMM>>>(out, N);
}

// round 7
// speedup vs baseline: 1.1852x; 1.0936x over previous
#include <cuda_runtime.h>
#include <cuda_bf16.h>
#include <math.h>
#include <stdint.h>

// ---------------- problem constants ----------------
#define N_MAXN    50000
#define NPAD      50048          // 391 * 128
#define MEM_DIM   100
#define RAW       64
#define TIN       20
#define D_MSG     292
#define KT1       400            // K per split term (392 real + 8 pad)
#define AK        800            // A row: [Ahi(400) | Alo(400)]
#define KTOT      1200           // GEMM K: [Ahi*Bhi | Ahi*Blo | Alo*Bhi]
#define JB        400            // B rows: j = channel*4 + group, channel<100

// ---------------- scratch ----------------
__device__ __nv_bfloat16 g_A[(size_t)NPAD * AK];    // ~80 MB
__device__ __nv_bfloat16 g_B[(size_t)JB * KTOT];    // ~0.96 MB
__device__ float         g_mem[(size_t)NPAD * MEM_DIM];

__device__ __forceinline__ uint32_t smem_u32(const void* p) {
    uint32_t a;
    asm("{ .reg .u64 t; cvta.to.shared.u64 t, %1; cvt.u32.u64 %0, t; }" : "=r"(a) : "l"(p));
    return a;
}
__device__ __forceinline__ void cp_async16(uint32_t dst, const void* src) {
    asm volatile("cp.async.cg.shared.global [%0], [%1], 16;" :: "r"(dst), "l"(src));
}
__device__ __forceinline__ void cp_commit() {
    asm volatile("cp.async.commit_group;" ::: "memory");
}
__device__ __forceinline__ void cp_wait_all() {
    asm volatile("cp.async.wait_group 0;" ::: "memory");
}
__device__ __forceinline__ void ldmx4(uint32_t* r, uint32_t addr) {
    asm volatile("ldmatrix.sync.aligned.m8n8.x4.shared.b16 {%0,%1,%2,%3}, [%4];"
        : "=r"(r[0]), "=r"(r[1]), "=r"(r[2]), "=r"(r[3]) : "r"(addr));
}
__device__ __forceinline__ void ldmx2(uint32_t* r, uint32_t addr) {
    asm volatile("ldmatrix.sync.aligned.m8n8.x2.shared.b16 {%0,%1}, [%2];"
        : "=r"(r[0]), "=r"(r[1]) : "r"(addr));
}
__device__ __forceinline__ void mma16816(float* d, const uint32_t* a, const uint32_t* b) {
    asm volatile(
        "mma.sync.aligned.m16n8k16.row.col.f32.bf16.bf16.f32 "
        "{%0,%1,%2,%3}, {%4,%5,%6,%7}, {%8,%9}, {%0,%1,%2,%3};"
        : "+f"(d[0]), "+f"(d[1]), "+f"(d[2]), "+f"(d[3])
        : "r"(a[0]), "r"(a[1]), "r"(a[2]), "r"(a[3]), "r"(b[0]), "r"(b[1]));
}
__device__ __forceinline__ void bsplit(float x, __nv_bfloat16& h, __nv_bfloat16& l) {
    h = __float2bfloat16(x);
    l = __float2bfloat16(x - __bfloat162float(h));
}

// ---------------------------------------------------------------------------
// Kernel 0: pack GRU weights -> g_B [400][1200] bf16, terms [Bhi|Blo|Bhi].
// Row j = c*4 + g  (c = channel 0..99, g: 0=r 1=z 2=gi_n 3=gh_n)
// ---------------------------------------------------------------------------
__global__ void buildB(const float* __restrict__ wih, const float* __restrict__ whh) {
    int idx = blockIdx.x * blockDim.x + threadIdx.x;
    if (idx >= JB * KTOT) return;
    int j = idx / KTOT, k = idx % KTOT;
    int c = j >> 2, g = j & 3;
    int t = k / KT1, kk = k % KT1;
    float v = 0.0f;
    if (kk < D_MSG) {
        if (g == 0) v = wih[c * D_MSG + kk];
        else if (g == 1) v = wih[(100 + c) * D_MSG + kk];
        else if (g == 2) v = wih[(200 + c) * D_MSG + kk];
    } else if (kk < D_MSG + MEM_DIM) {
        int m = kk - D_MSG;
        if (g == 0) v = whh[c * MEM_DIM + m];
        else if (g == 1) v = whh[(100 + c) * MEM_DIM + m];
        else if (g == 3) v = whh[(200 + c) * MEM_DIM + m];
    }
    __nv_bfloat16 h, l;
    bsplit(v, h, l);
    g_B[idx] = (t == 1) ? l : h;
}

// ---------------------------------------------------------------------------
// Kernel 1: per-node msg MLP + layernorms -> g_A row [hi(400)|lo(400)] + g_mem.
// ---------------------------------------------------------------------------
__global__ __launch_bounds__(64) void phase1(
    const int* __restrict__ n_id,
    const float* __restrict__ memory,
    const float* __restrict__ msgs,
    const float* __restrict__ w1, const float* __restrict__ b1,
    const float* __restrict__ w2, const float* __restrict__ b2,
    const float* __restrict__ lg, const float* __restrict__ lb,
    const float* __restrict__ lng, const float* __restrict__ lnb,
    int N)
{
    __shared__ float sm[RAW * TIN];
    __shared__ float sv[D_MSG];
    __shared__ float red[4];
    __shared__ float s_mu, s_rs;

    int i = blockIdx.x;
    int tid = threadIdx.x;
    size_t base = (size_t)i * AK;

    if (i >= N) {  // zero pad rows
        uint4 z = make_uint4(0, 0, 0, 0);
        uint4* dst = (uint4*)(g_A + base);
        for (int k = tid; k < AK / 8; k += 64) dst[k] = z;
        return;
    }
    int row = n_id[i];

    const float4* src4 = (const float4*)(msgs + (size_t)row * (RAW * TIN));
    float4* sm4 = (float4*)sm;
#pragma unroll
    for (int t = tid; t < RAW * TIN / 4; t += 64) sm4[t] = src4[t];
    const float* memrow = memory + (size_t)row * MEM_DIM;
    for (int c = tid; c < MEM_DIM; c += 64) sv[c] = memrow[c];
    __syncthreads();

    {
        const float* mr = sm + tid * TIN;
        float h[10];
#pragma unroll
        for (int j = 0; j < 10; j++) {
            float s = __ldg(b1 + j);
#pragma unroll
            for (int t = 0; t < TIN; t++) s += mr[t] * __ldg(w1 + j * TIN + t);
            h[j] = 0.5f * s * (1.0f + erff(s * 0.7071067811865476f));
        }
        float y[3];
#pragma unroll
        for (int o = 0; o < 3; o++) {
            float s = __ldg(b2 + o);
#pragma unroll
            for (int j = 0; j < 10; j++) s += h[j] * __ldg(w2 + o * 10 + j);
            y[o] = s;
        }
        float mu = (y[0] + y[1] + y[2]) * (1.0f / 3.0f);
        float d0 = y[0] - mu, d1 = y[1] - mu, d2 = y[2] - mu;
        float var = (d0 * d0 + d1 * d1 + d2 * d2) * (1.0f / 3.0f);
        float rs = rsqrtf(var + 1e-5f);
        sv[MEM_DIM + 3 * tid + 0] = d0 * rs * __ldg(lg + 0) + __ldg(lb + 0);
        sv[MEM_DIM + 3 * tid + 1] = d1 * rs * __ldg(lg + 1) + __ldg(lb + 1);
        sv[MEM_DIM + 3 * tid + 2] = d2 * rs * __ldg(lg + 2) + __ldg(lb + 2);
    }
    __syncthreads();

    float s1 = 0.0f, s2 = 0.0f;
    for (int k = tid; k < D_MSG; k += 64) { float v = sv[k]; s1 += v; s2 += v * v; }
#pragma unroll
    for (int o = 16; o > 0; o >>= 1) {
        s1 += __shfl_down_sync(0xFFFFFFFFu, s1, o);
        s2 += __shfl_down_sync(0xFFFFFFFFu, s2, o);
    }
    if ((tid & 31) == 0) { red[tid >> 5] = s1; red[2 + (tid >> 5)] = s2; }
    __syncthreads();
    if (tid == 0) {
        float t1 = red[0] + red[1];
        float t2 = red[2] + red[3];
        float mu = t1 * (1.0f / 292.0f);
        float var = t2 * (1.0f / 292.0f) - mu * mu;
        s_mu = mu;
        s_rs = rsqrtf(var + 1e-5f);
    }
    __syncthreads();

    float mu = s_mu, rs = s_rs;
    for (int k = tid; k < D_MSG; k += 64) {
        float v = (sv[k] - mu) * rs * __ldg(lng + k) + __ldg(lnb + k);
        __nv_bfloat16 h, l; bsplit(v, h, l);
        g_A[base + k] = h; g_A[base + KT1 + k] = l;
    }
    for (int c = tid; c < MEM_DIM; c += 64) {
        float v = sv[c];
        __nv_bfloat16 h, l; bsplit(v, h, l);
        g_A[base + D_MSG + c] = h; g_A[base + KT1 + D_MSG + c] = l;
        g_mem[(size_t)i * MEM_DIM + c] = v;
    }
    if (tid < 8) {
        __nv_bfloat16 z = __float2bfloat16(0.0f);
        g_A[base + 392 + tid] = z;
        g_A[base + KT1 + 392 + tid] = z;
    }
}

// ---------------------------------------------------------------------------
// Kernel 2: bf16 HMMA GEMM + register-fused GRU epilogue. Zero N-padding.
// BM=128 BN=80 BK=48, 256 threads, 8 warps (4x2, warp tile 32x40),
// cp.async double buffer. grid = (5 col-blocks fast, 391 row-blocks).
// ---------------------------------------------------------------------------
#define BM 128
#define BN 80
#define BK 48
#define LDS 56
#define NKT (KTOT / BK)   // 25
#define A_H (BM * LDS)    // 7168 halves
#define B_H (BN * LDS)    // 4480 halves
#define STG_H (A_H + B_H) // 11648 halves = 23296 B
#define SMEM_GEMM (2 * STG_H * 2)   // 46592 B

__global__ __launch_bounds__(256, 2) void gemm7(float* __restrict__ out, int N) {
    extern __shared__ __align__(16) uint16_t smx[];

    int tid = threadIdx.x;
    int lane = tid & 31, wid = tid >> 5;
    int wm = wid & 3, wn = wid >> 2;            // 4 x 2 warp grid
    int row0 = blockIdx.y * BM;
    int colblk = blockIdx.x;                    // channels [colblk*20, +20)
    int col0 = colblk * BN;

    const uint16_t* gA = (const uint16_t*)g_A;
    const uint16_t* gB = (const uint16_t*)g_B;

    float acc[2][5][4];
#pragma unroll
    for (int mf = 0; mf < 2; mf++)
#pragma unroll
        for (int nf = 0; nf < 5; nf++)
#pragma unroll
            for (int q = 0; q < 4; q++) acc[mf][nf][q] = 0.0f;

    // loader: A = 128 rows x 6 chunks (768), B = 80 x 6 (480); 1248 chunks.
    auto load_stage = [&](int stage, int k0) {
        uint16_t* As = smx + stage * STG_H;
        uint16_t* Bs = As + A_H;
#pragma unroll
        for (int q = 0; q < 5; q++) {
            int id = tid + q * 256;
            if (id < 768) {
                int r = id / 6, c = id % 6;
                int kk = k0 + c * 8;
                int ak = (kk < KT1) ? kk : kk - KT1;
                cp_async16(smem_u32(&As[r * LDS + c * 8]),
                           gA + (size_t)(row0 + r) * AK + ak);
            } else if (id < 1248) {
                int id2 = id - 768;
                int r = id2 / 6, c = id2 % 6;
                cp_async16(smem_u32(&Bs[r * LDS + c * 8]),
                           gB + (size_t)(col0 + r) * KTOT + k0 + c * 8);
            }
        }
        cp_commit();
    };

    load_stage(0, 0);

    for (int kt = 0; kt < NKT; kt++) {
        int buf = kt & 1;
        cp_wait_all();
        __syncthreads();
        if (kt + 1 < NKT) load_stage(buf ^ 1, (kt + 1) * BK);

        uint16_t* As = smx + buf * STG_H;
        uint16_t* Bs = As + A_H;
#pragma unroll
        for (int ks = 0; ks < 3; ks++) {
            int k0 = ks * 16;
            uint32_t a[2][4], b[5][2];
#pragma unroll
            for (int mf = 0; mf < 2; mf++) {
                int r = wm * 32 + mf * 16 + (lane & 15);
                int c = k0 + (lane >> 4) * 8;
                ldmx4(a[mf], smem_u32(&As[r * LDS + c]));
            }
#pragma unroll
            for (int pr = 0; pr < 2; pr++) {
                int r = wn * 40 + pr * 16 + (lane & 7) + ((lane >> 4) << 3);
                int c = k0 + ((lane >> 3) & 1) * 8;
                uint32_t bb[4];
                ldmx4(bb, smem_u32(&Bs[r * LDS + c]));
                b[2 * pr][0] = bb[0]; b[2 * pr][1] = bb[1];
                b[2 * pr + 1][0] = bb[2]; b[2 * pr + 1][1] = bb[3];
            }
            {   // last n-frag via x2 (lanes 0-15 addresses)
                int r = wn * 40 + 32 + (lane & 7);
                int c = k0 + ((lane >> 3) & 1) * 8;
                ldmx2(b[4], smem_u32(&Bs[r * LDS + c]));
            }
#pragma unroll
            for (int mf = 0; mf < 2; mf++)
#pragma unroll
                for (int nf = 0; nf < 5; nf++)
                    mma16816(acc[mf][nf], a[mf], b[nf]);
        }
        __syncthreads();
    }

    // Register-fused GRU epilogue.
    // j within block = wn*40 + nf*8 + (lane&3)*2 (+1). Channel = j>>2 (+col0>>2),
    // lane pairs (lane, lane^1) hold groups {0,1}/{2,3} of the same channel.
#pragma unroll
    for (int mf = 0; mf < 2; mf++) {
        int r0i = row0 + wm * 32 + mf * 16 + (lane >> 2);
#pragma unroll
        for (int nf = 0; nf < 5; nf++) {
            float n0 = __shfl_xor_sync(0xFFFFFFFFu, acc[mf][nf][0], 1);
            float n1 = __shfl_xor_sync(0xFFFFFFFFu, acc[mf][nf][1], 1);
            float n2 = __shfl_xor_sync(0xFFFFFFFFu, acc[mf][nf][2], 1);
            float n3 = __shfl_xor_sync(0xFFFFFFFFu, acc[mf][nf][3], 1);
            if (!(lane & 1)) {
                int ch = colblk * 20 + wn * 10 + nf * 2 + ((lane & 3) >> 1);
                if (ch < MEM_DIM) {
                    if (r0i < N) {
                        float rr = 1.0f / (1.0f + expf(-acc[mf][nf][0]));
                        float zz = 1.0f / (1.0f + expf(-acc[mf][nf][1]));
                        float nn = tanhf(fmaf(rr, n1, n0));
                        float m = g_mem[(size_t)r0i * MEM_DIM + ch];
                        out[(size_t)r0i * MEM_DIM + ch] = (1.0f - zz) * nn + zz * m;
                    }
                    int r1i = r0i + 8;
                    if (r1i < N) {
                        float rr = 1.0f / (1.0f + expf(-acc[mf][nf][2]));
                        float zz = 1.0f / (1.0f + expf(-acc[mf][nf][3]));
                        float nn = tanhf(fmaf(rr, n3, n2));
                        float m = g_mem[(size_t)r1i * MEM_DIM + ch];
                        out[(size_t)r1i * MEM_DIM + ch] = (1.0f - zz) * nn + zz * m;
                    }
                }
            }
        }
    }
}

// ---------------------------------------------------------------------------
extern "C" void kernel_launch(void* const* d_in, const int* in_sizes, int n_in,
                              void* d_out, int out_size) {
    const int*   n_id   = (const int*)d_in[0];
    const float* memory = (const float*)d_in[1];
    const float* msgs   = (const float*)d_in[2];
    const float* w1     = (const float*)d_in[3];
    const float* b1     = (const float*)d_in[4];
    const float* w2     = (const float*)d_in[5];
    const float* b2     = (const float*)d_in[6];
    const float* lg     = (const float*)d_in[7];
    const float* lb     = (const float*)d_in[8];
    const float* lng    = (const float*)d_in[9];
    const float* lnb    = (const float*)d_in[10];
    const float* wih    = (const float*)d_in[11];
    const float* whh    = (const float*)d_in[12];
    float* out = (float*)d_out;

    int N = in_sizes[0];
    if (N > N_MAXN) N = N_MAXN;

    cudaFuncSetAttribute(gemm7, cudaFuncAttributeMaxDynamicSharedMemorySize, SMEM_GEMM);

    buildB<<<(JB * KTOT + 255) / 256, 256>>>(wih, whh);
    phase1<<<NPAD, 64>>>(n_id, memory, msgs, w1, b1, w2, b2, lg, lb, lng, lnb, N);
    dim3 grid(5, NPAD / BM);   // col-block fast -> A shared in L2
    gemm7<<<grid, 256, SMEM_GEMM>>>(out, N);
}

// round 9
// speedup vs baseline: 1.2052x; 1.0169x over previous
#include <cuda_runtime.h>
#include <cuda_bf16.h>
#include <math.h>
#include <stdint.h>

// ---------------- problem constants ----------------
#define N_MAXN    50000
#define NPAD      50048          // 391 * 128
#define MEM_DIM   100
#define RAW       64
#define TIN       20
#define D_MSG     292
#define KT1       400            // K per split term (392 real + 8 pad)
#define AK        800            // A row: [Ahi(400) | Alo(400)]
#define KTOT      1200           // GEMM K: [Ahi*Bhi | Ahi*Blo | Alo*Bhi]
#define JB        400            // B rows: j = channel*4 + group, channel<100

// ---------------- scratch ----------------
__device__ __nv_bfloat16 g_A[(size_t)NPAD * AK];    // ~80 MB
__device__ __nv_bfloat16 g_B[(size_t)JB * KTOT];    // ~0.96 MB
__device__ float         g_mem[(size_t)NPAD * MEM_DIM];

__device__ __forceinline__ uint32_t smem_u32(const void* p) {
    uint32_t a;
    asm("{ .reg .u64 t; cvta.to.shared.u64 t, %1; cvt.u32.u64 %0, t; }" : "=r"(a) : "l"(p));
    return a;
}
__device__ __forceinline__ void cp_async16(uint32_t dst, const void* src) {
    asm volatile("cp.async.cg.shared.global [%0], [%1], 16;" :: "r"(dst), "l"(src));
}
__device__ __forceinline__ void cp_commit() {
    asm volatile("cp.async.commit_group;" ::: "memory");
}
__device__ __forceinline__ void cp_wait1() {
    asm volatile("cp.async.wait_group 1;" ::: "memory");
}
__device__ __forceinline__ void ldmx4(uint32_t* r, uint32_t addr) {
    asm volatile("ldmatrix.sync.aligned.m8n8.x4.shared.b16 {%0,%1,%2,%3}, [%4];"
        : "=r"(r[0]), "=r"(r[1]), "=r"(r[2]), "=r"(r[3]) : "r"(addr));
}
__device__ __forceinline__ void ldmx2(uint32_t* r, uint32_t addr) {
    asm volatile("ldmatrix.sync.aligned.m8n8.x2.shared.b16 {%0,%1}, [%2];"
        : "=r"(r[0]), "=r"(r[1]) : "r"(addr));
}
__device__ __forceinline__ void mma16816(float* d, const uint32_t* a, const uint32_t* b) {
    asm volatile(
        "mma.sync.aligned.m16n8k16.row.col.f32.bf16.bf16.f32 "
        "{%0,%1,%2,%3}, {%4,%5,%6,%7}, {%8,%9}, {%0,%1,%2,%3};"
        : "+f"(d[0]), "+f"(d[1]), "+f"(d[2]), "+f"(d[3])
        : "r"(a[0]), "r"(a[1]), "r"(a[2]), "r"(a[3]), "r"(b[0]), "r"(b[1]));
}
__device__ __forceinline__ void bsplit(float x, __nv_bfloat16& h, __nv_bfloat16& l) {
    h = __float2bfloat16(x);
    l = __float2bfloat16(x - __bfloat162float(h));
}

// ---------------------------------------------------------------------------
// Kernel 0: pack GRU weights -> g_B [400][1200] bf16, terms [Bhi|Blo|Bhi].
// Row j = c*4 + g  (c = channel 0..99, g: 0=r 1=z 2=gi_n 3=gh_n)
// ---------------------------------------------------------------------------
__global__ void buildB(const float* __restrict__ wih, const float* __restrict__ whh) {
    int idx = blockIdx.x * blockDim.x + threadIdx.x;
    if (idx >= JB * KTOT) return;
    int j = idx / KTOT, k = idx % KTOT;
    int c = j >> 2, g = j & 3;
    int t = k / KT1, kk = k % KT1;
    float v = 0.0f;
    if (kk < D_MSG) {
        if (g == 0) v = wih[c * D_MSG + kk];
        else if (g == 1) v = wih[(100 + c) * D_MSG + kk];
        else if (g == 2) v = wih[(200 + c) * D_MSG + kk];
    } else if (kk < D_MSG + MEM_DIM) {
        int m = kk - D_MSG;
        if (g == 0) v = whh[c * MEM_DIM + m];
        else if (g == 1) v = whh[(100 + c) * MEM_DIM + m];
        else if (g == 3) v = whh[(200 + c) * MEM_DIM + m];
    }
    __nv_bfloat16 h, l;
    bsplit(v, h, l);
    g_B[idx] = (t == 1) ? l : h;
}

// ---------------------------------------------------------------------------
// Kernel 1: per-node msg MLP + layernorms -> g_A row [hi(400)|lo(400)] + g_mem.
// ---------------------------------------------------------------------------
__global__ __launch_bounds__(64) void phase1(
    const int* __restrict__ n_id,
    const float* __restrict__ memory,
    const float* __restrict__ msgs,
    const float* __restrict__ w1, const float* __restrict__ b1,
    const float* __restrict__ w2, const float* __restrict__ b2,
    const float* __restrict__ lg, const float* __restrict__ lb,
    const float* __restrict__ lng, const float* __restrict__ lnb,
    int N)
{
    __shared__ float sm[RAW * TIN];
    __shared__ float sv[D_MSG];
    __shared__ float red[4];
    __shared__ float s_mu, s_rs;

    int i = blockIdx.x;
    int tid = threadIdx.x;
    size_t base = (size_t)i * AK;

    if (i >= N) {  // zero pad rows
        uint4 z = make_uint4(0, 0, 0, 0);
        uint4* dst = (uint4*)(g_A + base);
        for (int k = tid; k < AK / 8; k += 64) dst[k] = z;
        return;
    }
    int row = n_id[i];

    const float4* src4 = (const float4*)(msgs + (size_t)row * (RAW * TIN));
    float4* sm4 = (float4*)sm;
#pragma unroll
    for (int t = tid; t < RAW * TIN / 4; t += 64) sm4[t] = src4[t];
    const float* memrow = memory + (size_t)row * MEM_DIM;
    for (int c = tid; c < MEM_DIM; c += 64) sv[c] = memrow[c];
    __syncthreads();

    {
        const float* mr = sm + tid * TIN;
        float h[10];
#pragma unroll
        for (int j = 0; j < 10; j++) {
            float s = __ldg(b1 + j);
#pragma unroll
            for (int t = 0; t < TIN; t++) s += mr[t] * __ldg(w1 + j * TIN + t);
            h[j] = 0.5f * s * (1.0f + erff(s * 0.7071067811865476f));
        }
        float y[3];
#pragma unroll
        for (int o = 0; o < 3; o++) {
            float s = __ldg(b2 + o);
#pragma unroll
            for (int j = 0; j < 10; j++) s += h[j] * __ldg(w2 + o * 10 + j);
            y[o] = s;
        }
        float mu = (y[0] + y[1] + y[2]) * (1.0f / 3.0f);
        float d0 = y[0] - mu, d1 = y[1] - mu, d2 = y[2] - mu;
        float var = (d0 * d0 + d1 * d1 + d2 * d2) * (1.0f / 3.0f);
        float rs = rsqrtf(var + 1e-5f);
        sv[MEM_DIM + 3 * tid + 0] = d0 * rs * __ldg(lg + 0) + __ldg(lb + 0);
        sv[MEM_DIM + 3 * tid + 1] = d1 * rs * __ldg(lg + 1) + __ldg(lb + 1);
        sv[MEM_DIM + 3 * tid + 2] = d2 * rs * __ldg(lg + 2) + __ldg(lb + 2);
    }
    __syncthreads();

    float s1 = 0.0f, s2 = 0.0f;
    for (int k = tid; k < D_MSG; k += 64) { float v = sv[k]; s1 += v; s2 += v * v; }
#pragma unroll
    for (int o = 16; o > 0; o >>= 1) {
        s1 += __shfl_down_sync(0xFFFFFFFFu, s1, o);
        s2 += __shfl_down_sync(0xFFFFFFFFu, s2, o);
    }
    if ((tid & 31) == 0) { red[tid >> 5] = s1; red[2 + (tid >> 5)] = s2; }
    __syncthreads();
    if (tid == 0) {
        float t1 = red[0] + red[1];
        float t2 = red[2] + red[3];
        float mu = t1 * (1.0f / 292.0f);
        float var = t2 * (1.0f / 292.0f) - mu * mu;
        s_mu = mu;
        s_rs = rsqrtf(var + 1e-5f);
    }
    __syncthreads();

    float mu = s_mu, rs = s_rs;
    for (int k = tid; k < D_MSG; k += 64) {
        float v = (sv[k] - mu) * rs * __ldg(lng + k) + __ldg(lnb + k);
        __nv_bfloat16 h, l; bsplit(v, h, l);
        g_A[base + k] = h; g_A[base + KT1 + k] = l;
    }
    for (int c = tid; c < MEM_DIM; c += 64) {
        float v = sv[c];
        __nv_bfloat16 h, l; bsplit(v, h, l);
        g_A[base + D_MSG + c] = h; g_A[base + KT1 + D_MSG + c] = l;
        g_mem[(size_t)i * MEM_DIM + c] = v;
    }
    if (tid < 8) {
        __nv_bfloat16 z = __float2bfloat16(0.0f);
        g_A[base + 392 + tid] = z;
        g_A[base + KT1 + 392 + tid] = z;
    }
}

// ---------------------------------------------------------------------------
// Kernel 2: bf16 HMMA GEMM + register-fused GRU epilogue.
// BM=128 BN=80 BK=48, 256 threads, 8 warps (4x2, warp tile 32x40).
// 3-stage cp.async pipeline (wait_group 1), one __syncthreads per kt.
// ---------------------------------------------------------------------------
#define BM 128
#define BN 80
#define BK 48
#define LDS 56
#define NKT (KTOT / BK)   // 25
#define A_H (BM * LDS)    // 7168 halves
#define B_H (BN * LDS)    // 4480 halves
#define STG_H (A_H + B_H) // 11648 halves = 23296 B
#define SMEM_GEMM (3 * STG_H * 2)   // 69888 B

__global__ __launch_bounds__(256, 2) void gemm9(float* __restrict__ out, int N) {
    extern __shared__ __align__(16) uint16_t smx[];

    int tid = threadIdx.x;
    int lane = tid & 31, wid = tid >> 5;
    int wm = wid & 3, wn = wid >> 2;            // 4 x 2 warp grid
    int row0 = blockIdx.y * BM;
    int colblk = blockIdx.x;                    // channels [colblk*20, +20)
    int col0 = colblk * BN;

    const uint16_t* gA = (const uint16_t*)g_A;
    const uint16_t* gB = (const uint16_t*)g_B;

    float acc[2][5][4];
#pragma unroll
    for (int mf = 0; mf < 2; mf++)
#pragma unroll
        for (int nf = 0; nf < 5; nf++)
#pragma unroll
            for (int q = 0; q < 4; q++) acc[mf][nf][q] = 0.0f;

    // ---- hoisted loader geometry: up to 5 chunks/thread (A:768, B:480) ----
    const uint16_t* gsrc[5];
    uint32_t sdst[5];
    int coff[5];
    bool isA[5], valid[5];
#pragma unroll
    for (int q = 0; q < 5; q++) {
        int id = tid + q * 256;
        valid[q] = (id < 1248);
        if (id < 768) {
            int r = id / 6, c = id % 6;
            isA[q] = true; coff[q] = c * 8;
            gsrc[q] = gA + (size_t)(row0 + r) * AK;
            sdst[q] = r * LDS + c * 8;
        } else if (id < 1248) {
            int id2 = id - 768;
            int r = id2 / 6, c = id2 % 6;
            isA[q] = false; coff[q] = c * 8;
            gsrc[q] = gB + (size_t)(col0 + r) * KTOT + c * 8;
            sdst[q] = A_H + r * LDS + c * 8;
        } else {
            isA[q] = false; coff[q] = 0; gsrc[q] = gB; sdst[q] = 0;
        }
    }
    uint32_t sbase = smem_u32(smx);

    auto load_stage = [&](int stage, int k0) {
        uint32_t soff = sbase + (uint32_t)(stage * STG_H) * 2;
#pragma unroll
        for (int q = 0; q < 5; q++) {
            if (!valid[q]) continue;
            const uint16_t* src;
            if (isA[q]) {
                int kk = k0 + coff[q];
                int ak = (kk < KT1) ? kk : kk - KT1;
                src = gsrc[q] + ak;
            } else {
                src = gsrc[q] + k0;
            }
            cp_async16(soff + sdst[q] * 2, src);
        }
        cp_commit();
    };

    load_stage(0, 0);
    load_stage(1, BK);

    for (int kt = 0; kt < NKT; kt++) {
        int buf = kt % 3;
        cp_wait1();
        __syncthreads();
        if (kt + 2 < NKT) load_stage((kt + 2) % 3, (kt + 2) * BK);

        uint16_t* As = smx + buf * STG_H;
        uint16_t* Bs = As + A_H;
#pragma unroll
        for (int ks = 0; ks < 3; ks++) {
            int k0 = ks * 16;
            uint32_t a[2][4], b[5][2];
#pragma unroll
            for (int mf = 0; mf < 2; mf++) {
                int r = wm * 32 + mf * 16 + (lane & 15);
                int c = k0 + (lane >> 4) * 8;
                ldmx4(a[mf], smem_u32(&As[r * LDS + c]));
            }
#pragma unroll
            for (int pr = 0; pr < 2; pr++) {
                int r = wn * 40 + pr * 16 + (lane & 7) + ((lane >> 4) << 3);
                int c = k0 + ((lane >> 3) & 1) * 8;
                uint32_t bb[4];
                ldmx4(bb, smem_u32(&Bs[r * LDS + c]));
                b[2 * pr][0] = bb[0]; b[2 * pr][1] = bb[1];
                b[2 * pr + 1][0] = bb[2]; b[2 * pr + 1][1] = bb[3];
            }
            {   // last n-frag via x2
                int r = wn * 40 + 32 + (lane & 7);
                int c = k0 + ((lane >> 3) & 1) * 8;
                ldmx2(b[4], smem_u32(&Bs[r * LDS + c]));
            }
#pragma unroll
            for (int mf = 0; mf < 2; mf++)
#pragma unroll
                for (int nf = 0; nf < 5; nf++)
                    mma16816(acc[mf][nf], a[mf], b[nf]);
        }
    }

    // Register-fused GRU epilogue.
#pragma unroll
    for (int mf = 0; mf < 2; mf++) {
        int r0i = row0 + wm * 32 + mf * 16 + (lane >> 2);
#pragma unroll
        for (int nf = 0; nf < 5; nf++) {
            float n0 = __shfl_xor_sync(0xFFFFFFFFu, acc[mf][nf][0], 1);
            float n1 = __shfl_xor_sync(0xFFFFFFFFu, acc[mf][nf][1], 1);
            float n2 = __shfl_xor_sync(0xFFFFFFFFu, acc[mf][nf][2], 1);
            float n3 = __shfl_xor_sync(0xFFFFFFFFu, acc[mf][nf][3], 1);
            if (!(lane & 1)) {
                int ch = colblk * 20 + wn * 10 + nf * 2 + ((lane & 3) >> 1);
                if (ch < MEM_DIM) {
                    if (r0i < N) {
                        float rr = 1.0f / (1.0f + expf(-acc[mf][nf][0]));
                        float zz = 1.0f / (1.0f + expf(-acc[mf][nf][1]));
                        float nn = tanhf(fmaf(rr, n1, n0));
                        float m = g_mem[(size_t)r0i * MEM_DIM + ch];
                        out[(size_t)r0i * MEM_DIM + ch] = (1.0f - zz) * nn + zz * m;
                    }
                    int r1i = r0i + 8;
                    if (r1i < N) {
                        float rr = 1.0f / (1.0f + expf(-acc[mf][nf][2]));
                        float zz = 1.0f / (1.0f + expf(-acc[mf][nf][3]));
                        float nn = tanhf(fmaf(rr, n3, n2));
                        float m = g_mem[(size_t)r1i * MEM_DIM + ch];
                        out[(size_t)r1i * MEM_DIM + ch] = (1.0f - zz) * nn + zz * m;
                    }
                }
            }
        }
    }
}

// ---------------------------------------------------------------------------
extern "C" void kernel_launch(void* const* d_in, const int* in_sizes, int n_in,
                              void* d_out, int out_size) {
    const int*   n_id   = (const int*)d_in[0];
    const float* memory = (const float*)d_in[1];
    const float* msgs   = (const float*)d_in[2];
    const float* w1     = (const float*)d_in[3];
    const float* b1     = (const float*)d_in[4];
    const float* w2     = (const float*)d_in[5];
    const float* b2     = (const float*)d_in[6];
    const float* lg     = (const float*)d_in[7];
    const float* lb     = (const float*)d_in[8];
    const float* lng    = (const float*)d_in[9];
    const float* lnb    = (const float*)d_in[10];
    const float* wih    = (const float*)d_in[11];
    const float* whh    = (const float*)d_in[12];
    float* out = (float*)d_out;

    int N = in_sizes[0];
    if (N > N_MAXN) N = N_MAXN;

    cudaFuncSetAttribute(gemm9, cudaFuncAttributeMaxDynamicSharedMemorySize, SMEM_GEMM);

    buildB<<<(JB * KTOT + 255) / 256, 256>>>(wih, whh);
    phase1<<<NPAD, 64>>>(n_id, memory, msgs, w1, b1, w2, b2, lg, lb, lng, lnb, N);
    dim3 grid(5, NPAD / BM);   // col-block fast -> A shared in L2
    gemm9<<<grid, 256, SMEM_GEMM>>>(out, N);
}

// round 10
// speedup vs baseline: 1.4387x; 1.1937x over previous
#include <cuda_runtime.h>
#include <cuda_fp16.h>
#include <math.h>
#include <stdint.h>

// ---------------- problem constants ----------------
#define N_MAXN    50000
#define NPAD      50048          // 391 * 128
#define MEM_DIM   100
#define RAW       64
#define TIN       20
#define D_MSG     292
#define KT1       400            // K per term (392 real + 8 pad)
#define AK        800            // A row: [Ahi(400) | Alo(400)]  == GEMM K layout
#define KTOT      800            // GEMM K: [Ahi*B | Alo*B]
#define JB        400            // B rows: j = channel*4 + group, channel<100

// ---------------- scratch ----------------
__device__ __half g_A[(size_t)NPAD * AK];    // ~80 MB
__device__ __half g_B[(size_t)JB * KTOT];    // ~0.64 MB  (B duplicated twice over K)
__device__ float  g_mem[(size_t)NPAD * MEM_DIM];

__device__ __forceinline__ uint32_t smem_u32(const void* p) {
    uint32_t a;
    asm("{ .reg .u64 t; cvta.to.shared.u64 t, %1; cvt.u32.u64 %0, t; }" : "=r"(a) : "l"(p));
    return a;
}
__device__ __forceinline__ void cp_async16(uint32_t dst, const void* src) {
    asm volatile("cp.async.cg.shared.global [%0], [%1], 16;" :: "r"(dst), "l"(src));
}
__device__ __forceinline__ void cp_commit() {
    asm volatile("cp.async.commit_group;" ::: "memory");
}
__device__ __forceinline__ void cp_wait1() {
    asm volatile("cp.async.wait_group 1;" ::: "memory");
}
__device__ __forceinline__ void ldmx4(uint32_t* r, uint32_t addr) {
    asm volatile("ldmatrix.sync.aligned.m8n8.x4.shared.b16 {%0,%1,%2,%3}, [%4];"
        : "=r"(r[0]), "=r"(r[1]), "=r"(r[2]), "=r"(r[3]) : "r"(addr));
}
__device__ __forceinline__ void ldmx2(uint32_t* r, uint32_t addr) {
    asm volatile("ldmatrix.sync.aligned.m8n8.x2.shared.b16 {%0,%1}, [%2];"
        : "=r"(r[0]), "=r"(r[1]) : "r"(addr));
}
__device__ __forceinline__ void mma16816(float* d, const uint32_t* a, const uint32_t* b) {
    asm volatile(
        "mma.sync.aligned.m16n8k16.row.col.f32.f16.f16.f32 "
        "{%0,%1,%2,%3}, {%4,%5,%6,%7}, {%8,%9}, {%0,%1,%2,%3};"
        : "+f"(d[0]), "+f"(d[1]), "+f"(d[2]), "+f"(d[3])
        : "r"(a[0]), "r"(a[1]), "r"(a[2]), "r"(a[3]), "r"(b[0]), "r"(b[1]));
}
__device__ __forceinline__ void hsplit(float x, __half& h, __half& l) {
    h = __float2half_rn(x);
    l = __float2half_rn(x - __half2float(h));
}

// ---------------------------------------------------------------------------
// Kernel 0: pack GRU weights -> g_B [400][800] fp16, duplicated [B|B].
// Row j = c*4 + g  (c = channel 0..99, g: 0=r 1=z 2=gi_n 3=gh_n)
// kk = k%400: [0,292)=w_ih, [292,392)=w_hh, else 0.
// ---------------------------------------------------------------------------
__global__ void buildB(const float* __restrict__ wih, const float* __restrict__ whh) {
    int idx = blockIdx.x * blockDim.x + threadIdx.x;
    if (idx >= JB * KTOT) return;
    int j = idx / KTOT, k = idx % KTOT;
    int c = j >> 2, g = j & 3;
    int kk = (k < KT1) ? k : k - KT1;
    float v = 0.0f;
    if (kk < D_MSG) {
        if (g == 0) v = wih[c * D_MSG + kk];
        else if (g == 1) v = wih[(100 + c) * D_MSG + kk];
        else if (g == 2) v = wih[(200 + c) * D_MSG + kk];
    } else if (kk < D_MSG + MEM_DIM) {
        int m = kk - D_MSG;
        if (g == 0) v = whh[c * MEM_DIM + m];
        else if (g == 1) v = whh[(100 + c) * MEM_DIM + m];
        else if (g == 3) v = whh[(200 + c) * MEM_DIM + m];
    }
    g_B[idx] = __float2half_rn(v);
}

// ---------------------------------------------------------------------------
// Kernel 1: per-node msg MLP + layernorms -> g_A row [hi(400)|lo(400)] + g_mem.
// ---------------------------------------------------------------------------
__global__ __launch_bounds__(64) void phase1(
    const int* __restrict__ n_id,
    const float* __restrict__ memory,
    const float* __restrict__ msgs,
    const float* __restrict__ w1, const float* __restrict__ b1,
    const float* __restrict__ w2, const float* __restrict__ b2,
    const float* __restrict__ lg, const float* __restrict__ lb,
    const float* __restrict__ lng, const float* __restrict__ lnb,
    int N)
{
    __shared__ float sm[RAW * TIN];
    __shared__ float sv[D_MSG];
    __shared__ float red[4];
    __shared__ float s_mu, s_rs;

    int i = blockIdx.x;
    int tid = threadIdx.x;
    size_t base = (size_t)i * AK;

    if (i >= N) {  // zero pad rows
        uint4 z = make_uint4(0, 0, 0, 0);
        uint4* dst = (uint4*)(g_A + base);
        for (int k = tid; k < AK / 8; k += 64) dst[k] = z;
        return;
    }
    int row = n_id[i];

    const float4* src4 = (const float4*)(msgs + (size_t)row * (RAW * TIN));
    float4* sm4 = (float4*)sm;
#pragma unroll
    for (int t = tid; t < RAW * TIN / 4; t += 64) sm4[t] = src4[t];
    const float* memrow = memory + (size_t)row * MEM_DIM;
    for (int c = tid; c < MEM_DIM; c += 64) sv[c] = memrow[c];
    __syncthreads();

    {
        const float* mr = sm + tid * TIN;
        float h[10];
#pragma unroll
        for (int j = 0; j < 10; j++) {
            float s = __ldg(b1 + j);
#pragma unroll
            for (int t = 0; t < TIN; t++) s += mr[t] * __ldg(w1 + j * TIN + t);
            h[j] = 0.5f * s * (1.0f + erff(s * 0.7071067811865476f));
        }
        float y[3];
#pragma unroll
        for (int o = 0; o < 3; o++) {
            float s = __ldg(b2 + o);
#pragma unroll
            for (int j = 0; j < 10; j++) s += h[j] * __ldg(w2 + o * 10 + j);
            y[o] = s;
        }
        float mu = (y[0] + y[1] + y[2]) * (1.0f / 3.0f);
        float d0 = y[0] - mu, d1 = y[1] - mu, d2 = y[2] - mu;
        float var = (d0 * d0 + d1 * d1 + d2 * d2) * (1.0f / 3.0f);
        float rs = rsqrtf(var + 1e-5f);
        sv[MEM_DIM + 3 * tid + 0] = d0 * rs * __ldg(lg + 0) + __ldg(lb + 0);
        sv[MEM_DIM + 3 * tid + 1] = d1 * rs * __ldg(lg + 1) + __ldg(lb + 1);
        sv[MEM_DIM + 3 * tid + 2] = d2 * rs * __ldg(lg + 2) + __ldg(lb + 2);
    }
    __syncthreads();

    float s1 = 0.0f, s2 = 0.0f;
    for (int k = tid; k < D_MSG; k += 64) { float v = sv[k]; s1 += v; s2 += v * v; }
#pragma unroll
    for (int o = 16; o > 0; o >>= 1) {
        s1 += __shfl_down_sync(0xFFFFFFFFu, s1, o);
        s2 += __shfl_down_sync(0xFFFFFFFFu, s2, o);
    }
    if ((tid & 31) == 0) { red[tid >> 5] = s1; red[2 + (tid >> 5)] = s2; }
    __syncthreads();
    if (tid == 0) {
        float t1 = red[0] + red[1];
        float t2 = red[2] + red[3];
        float mu = t1 * (1.0f / 292.0f);
        float var = t2 * (1.0f / 292.0f) - mu * mu;
        s_mu = mu;
        s_rs = rsqrtf(var + 1e-5f);
    }
    __syncthreads();

    float mu = s_mu, rs = s_rs;
    for (int k = tid; k < D_MSG; k += 64) {
        float v = (sv[k] - mu) * rs * __ldg(lng + k) + __ldg(lnb + k);
        __half h, l; hsplit(v, h, l);
        g_A[base + k] = h; g_A[base + KT1 + k] = l;
    }
    for (int c = tid; c < MEM_DIM; c += 64) {
        float v = sv[c];
        __half h, l; hsplit(v, h, l);
        g_A[base + D_MSG + c] = h; g_A[base + KT1 + D_MSG + c] = l;
        g_mem[(size_t)i * MEM_DIM + c] = v;
    }
    if (tid < 8) {
        __half z = __float2half_rn(0.0f);
        g_A[base + 392 + tid] = z;
        g_A[base + KT1 + 392 + tid] = z;
    }
}

// ---------------------------------------------------------------------------
// Kernel 2: fp16 HMMA GEMM + register-fused GRU epilogue.
// BM=128 BN=80 BK=32, 256 threads, 8 warps (4x2, warp tile 32x40).
// 3-stage cp.async pipeline (wait_group 1). K=800 (two-term fp16 split).
// ---------------------------------------------------------------------------
#define BM 128
#define BN 80
#define BK 32
#define LDS 40
#define NKT (KTOT / BK)   // 25
#define A_H (BM * LDS)    // 5120 halves
#define B_H (BN * LDS)    // 3200 halves
#define STG_H (A_H + B_H) // 8320 halves = 16640 B
#define SMEM_GEMM (3 * STG_H * 2)   // 49920 B

__global__ __launch_bounds__(256, 2) void gemm10(float* __restrict__ out, int N) {
    extern __shared__ __align__(16) uint16_t smx[];

    int tid = threadIdx.x;
    int lane = tid & 31, wid = tid >> 5;
    int wm = wid & 3, wn = wid >> 2;            // 4 x 2 warp grid
    int row0 = blockIdx.y * BM;
    int colblk = blockIdx.x;                    // channels [colblk*20, +20)
    int col0 = colblk * BN;

    const uint16_t* gA = (const uint16_t*)g_A;
    const uint16_t* gB = (const uint16_t*)g_B;

    float acc[2][5][4];
#pragma unroll
    for (int mf = 0; mf < 2; mf++)
#pragma unroll
        for (int nf = 0; nf < 5; nf++)
#pragma unroll
            for (int q = 0; q < 4; q++) acc[mf][nf][q] = 0.0f;

    // ---- hoisted loader geometry: up to 4 chunks/thread (A:512, B:320) ----
    const uint16_t* gsrc[4];   // base at k=0 (incl. chunk col offset)
    uint32_t sdst[4];
    bool valid[4];
#pragma unroll
    for (int q = 0; q < 4; q++) {
        int id = tid + q * 256;
        valid[q] = (id < 832);
        if (id < 512) {
            int r = id >> 2, c = id & 3;
            gsrc[q] = gA + (size_t)(row0 + r) * AK + c * 8;
            sdst[q] = r * LDS + c * 8;
        } else if (id < 832) {
            int id2 = id - 512;
            int r = id2 >> 2, c = id2 & 3;
            gsrc[q] = gB + (size_t)(col0 + r) * KTOT + c * 8;
            sdst[q] = A_H + r * LDS + c * 8;
        } else {
            gsrc[q] = gB; sdst[q] = 0;
        }
    }
    uint32_t sbase = smem_u32(smx);

    auto load_stage = [&](int stage, int k0) {
        uint32_t soff = sbase + (uint32_t)(stage * STG_H) * 2;
#pragma unroll
        for (int q = 0; q < 4; q++) {
            if (!valid[q]) continue;
            cp_async16(soff + sdst[q] * 2, gsrc[q] + k0);
        }
        cp_commit();
    };

    load_stage(0, 0);
    load_stage(1, BK);

    for (int kt = 0; kt < NKT; kt++) {
        int buf = kt % 3;
        cp_wait1();
        __syncthreads();
        if (kt + 2 < NKT) load_stage((kt + 2) % 3, (kt + 2) * BK);

        uint16_t* As = smx + buf * STG_H;
        uint16_t* Bs = As + A_H;
#pragma unroll
        for (int ks = 0; ks < 2; ks++) {
            int k0 = ks * 16;
            uint32_t a[2][4], b[5][2];
#pragma unroll
            for (int mf = 0; mf < 2; mf++) {
                int r = wm * 32 + mf * 16 + (lane & 15);
                int c = k0 + (lane >> 4) * 8;
                ldmx4(a[mf], smem_u32(&As[r * LDS + c]));
            }
#pragma unroll
            for (int pr = 0; pr < 2; pr++) {
                int r = wn * 40 + pr * 16 + (lane & 7) + ((lane >> 4) << 3);
                int c = k0 + ((lane >> 3) & 1) * 8;
                uint32_t bb[4];
                ldmx4(bb, smem_u32(&Bs[r * LDS + c]));
                b[2 * pr][0] = bb[0]; b[2 * pr][1] = bb[1];
                b[2 * pr + 1][0] = bb[2]; b[2 * pr + 1][1] = bb[3];
            }
            {   // last n-frag via x2
                int r = wn * 40 + 32 + (lane & 7);
                int c = k0 + ((lane >> 3) & 1) * 8;
                ldmx2(b[4], smem_u32(&Bs[r * LDS + c]));
            }
#pragma unroll
            for (int mf = 0; mf < 2; mf++)
#pragma unroll
                for (int nf = 0; nf < 5; nf++)
                    mma16816(acc[mf][nf], a[mf], b[nf]);
        }
    }

    // Register-fused GRU epilogue.
#pragma unroll
    for (int mf = 0; mf < 2; mf++) {
        int r0i = row0 + wm * 32 + mf * 16 + (lane >> 2);
#pragma unroll
        for (int nf = 0; nf < 5; nf++) {
            float n0 = __shfl_xor_sync(0xFFFFFFFFu, acc[mf][nf][0], 1);
            float n1 = __shfl_xor_sync(0xFFFFFFFFu, acc[mf][nf][1], 1);
            float n2 = __shfl_xor_sync(0xFFFFFFFFu, acc[mf][nf][2], 1);
            float n3 = __shfl_xor_sync(0xFFFFFFFFu, acc[mf][nf][3], 1);
            if (!(lane & 1)) {
                int ch = colblk * 20 + wn * 10 + nf * 2 + ((lane & 3) >> 1);
                if (ch < MEM_DIM) {
                    if (r0i < N) {
                        float rr = 1.0f / (1.0f + expf(-acc[mf][nf][0]));
                        float zz = 1.0f / (1.0f + expf(-acc[mf][nf][1]));
                        float nn = tanhf(fmaf(rr, n1, n0));
                        float m = g_mem[(size_t)r0i * MEM_DIM + ch];
                        out[(size_t)r0i * MEM_DIM + ch] = (1.0f - zz) * nn + zz * m;
                    }
                    int r1i = r0i + 8;
                    if (r1i < N) {
                        float rr = 1.0f / (1.0f + expf(-acc[mf][nf][2]));
                        float zz = 1.0f / (1.0f + expf(-acc[mf][nf][3]));
                        float nn = tanhf(fmaf(rr, n3, n2));
                        float m = g_mem[(size_t)r1i * MEM_DIM + ch];
                        out[(size_t)r1i * MEM_DIM + ch] = (1.0f - zz) * nn + zz * m;
                    }
                }
            }
        }
    }
}

// ---------------------------------------------------------------------------
extern "C" void kernel_launch(void* const* d_in, const int* in_sizes, int n_in,
                              void* d_out, int out_size) {
    const int*   n_id   = (const int*)d_in[0];
    const float* memory = (const float*)d_in[1];
    const float* msgs   = (const float*)d_in[2];
    const float* w1     = (const float*)d_in[3];
    const float* b1     = (const float*)d_in[4];
    const float* w2     = (const float*)d_in[5];
    const float* b2     = (const float*)d_in[6];
    const float* lg     = (const float*)d_in[7];
    const float* lb     = (const float*)d_in[8];
    const float* lng    = (const float*)d_in[9];
    const float* lnb    = (const float*)d_in[10];
    const float* wih    = (const float*)d_in[11];
    const float* whh    = (const float*)d_in[12];
    float* out = (float*)d_out;

    int N = in_sizes[0];
    if (N > N_MAXN) N = N_MAXN;

    cudaFuncSetAttribute(gemm10, cudaFuncAttributeMaxDynamicSharedMemorySize, SMEM_GEMM);

    buildB<<<(JB * KTOT + 255) / 256, 256>>>(wih, whh);
    phase1<<<NPAD, 64>>>(n_id, memory, msgs, w1, b1, w2, b2, lg, lb, lng, lnb, N);
    dim3 grid(5, NPAD / BM);   // col-block fast -> A shared in L2
    gemm10<<<grid, 256, SMEM_GEMM>>>(out, N);
}

// round 11
// speedup vs baseline: 1.7788x; 1.2364x over previous
#include <cuda_runtime.h>
#include <cuda_fp16.h>
#include <math.h>
#include <stdint.h>

// ---------------- problem constants ----------------
#define N_MAXN    50000
#define NPAD      50048          // 391 * 128
#define MEM_DIM   100
#define RAW       64
#define TIN       20
#define D_MSG     292
#define KREAL     392            // 292 x + 100 mem
#define AK        416            // K padded to 13*32
#define KTOT      416
#define JB        400            // B rows: j = channel*4 + group, channel<100

// ---------------- scratch ----------------
__device__ __half g_A[(size_t)NPAD * AK];    // ~42 MB
__device__ __half g_B[(size_t)JB * KTOT];    // ~0.33 MB
__device__ float  g_mem[(size_t)NPAD * MEM_DIM];

__device__ __forceinline__ uint32_t smem_u32(const void* p) {
    uint32_t a;
    asm("{ .reg .u64 t; cvta.to.shared.u64 t, %1; cvt.u32.u64 %0, t; }" : "=r"(a) : "l"(p));
    return a;
}
__device__ __forceinline__ void cp_async16(uint32_t dst, const void* src) {
    asm volatile("cp.async.cg.shared.global [%0], [%1], 16;" :: "r"(dst), "l"(src));
}
__device__ __forceinline__ void cp_commit() {
    asm volatile("cp.async.commit_group;" ::: "memory");
}
__device__ __forceinline__ void cp_wait1() {
    asm volatile("cp.async.wait_group 1;" ::: "memory");
}
__device__ __forceinline__ void ldmx4(uint32_t* r, uint32_t addr) {
    asm volatile("ldmatrix.sync.aligned.m8n8.x4.shared.b16 {%0,%1,%2,%3}, [%4];"
        : "=r"(r[0]), "=r"(r[1]), "=r"(r[2]), "=r"(r[3]) : "r"(addr));
}
__device__ __forceinline__ void ldmx2(uint32_t* r, uint32_t addr) {
    asm volatile("ldmatrix.sync.aligned.m8n8.x2.shared.b16 {%0,%1}, [%2];"
        : "=r"(r[0]), "=r"(r[1]) : "r"(addr));
}
__device__ __forceinline__ void mma16816(float* d, const uint32_t* a, const uint32_t* b) {
    asm volatile(
        "mma.sync.aligned.m16n8k16.row.col.f32.f16.f16.f32 "
        "{%0,%1,%2,%3}, {%4,%5,%6,%7}, {%8,%9}, {%0,%1,%2,%3};"
        : "+f"(d[0]), "+f"(d[1]), "+f"(d[2]), "+f"(d[3])
        : "r"(a[0]), "r"(a[1]), "r"(a[2]), "r"(a[3]), "r"(b[0]), "r"(b[1]));
}

// ---------------------------------------------------------------------------
// Kernel 0: pack GRU weights -> g_B [400][416] fp16.
// Row j = c*4 + g  (c = channel 0..99, g: 0=r 1=z 2=gi_n 3=gh_n)
// k: [0,292)=w_ih, [292,392)=w_hh, [392,416)=0.
// ---------------------------------------------------------------------------
__global__ void buildB(const float* __restrict__ wih, const float* __restrict__ whh) {
    int idx = blockIdx.x * blockDim.x + threadIdx.x;
    if (idx >= JB * KTOT) return;
    int j = idx / KTOT, k = idx % KTOT;
    int c = j >> 2, g = j & 3;
    float v = 0.0f;
    if (k < D_MSG) {
        if (g == 0) v = wih[c * D_MSG + k];
        else if (g == 1) v = wih[(100 + c) * D_MSG + k];
        else if (g == 2) v = wih[(200 + c) * D_MSG + k];
    } else if (k < KREAL) {
        int m = k - D_MSG;
        if (g == 0) v = whh[c * MEM_DIM + m];
        else if (g == 1) v = whh[(100 + c) * MEM_DIM + m];
        else if (g == 3) v = whh[(200 + c) * MEM_DIM + m];
    }
    g_B[idx] = __float2half_rn(v);
}

// ---------------------------------------------------------------------------
// Kernel 1: per-node msg MLP + layernorms -> g_A row fp16[416] + g_mem.
// ---------------------------------------------------------------------------
__global__ __launch_bounds__(64) void phase1(
    const int* __restrict__ n_id,
    const float* __restrict__ memory,
    const float* __restrict__ msgs,
    const float* __restrict__ w1, const float* __restrict__ b1,
    const float* __restrict__ w2, const float* __restrict__ b2,
    const float* __restrict__ lg, const float* __restrict__ lb,
    const float* __restrict__ lng, const float* __restrict__ lnb,
    int N)
{
    __shared__ float sm[RAW * TIN];
    __shared__ float sv[D_MSG];
    __shared__ float red[4];
    __shared__ float s_mu, s_rs;

    int i = blockIdx.x;
    int tid = threadIdx.x;
    size_t base = (size_t)i * AK;

    if (i >= N) {  // zero pad rows (416/8 = 52 uint4)
        uint4 z = make_uint4(0, 0, 0, 0);
        uint4* dst = (uint4*)(g_A + base);
        for (int k = tid; k < AK / 8; k += 64) dst[k] = z;
        return;
    }
    int row = n_id[i];

    const float4* src4 = (const float4*)(msgs + (size_t)row * (RAW * TIN));
    float4* sm4 = (float4*)sm;
#pragma unroll
    for (int t = tid; t < RAW * TIN / 4; t += 64) sm4[t] = src4[t];
    const float* memrow = memory + (size_t)row * MEM_DIM;
    for (int c = tid; c < MEM_DIM; c += 64) sv[c] = memrow[c];
    __syncthreads();

    {
        const float* mr = sm + tid * TIN;
        float h[10];
#pragma unroll
        for (int j = 0; j < 10; j++) {
            float s = __ldg(b1 + j);
#pragma unroll
            for (int t = 0; t < TIN; t++) s += mr[t] * __ldg(w1 + j * TIN + t);
            h[j] = 0.5f * s * (1.0f + erff(s * 0.7071067811865476f));
        }
        float y[3];
#pragma unroll
        for (int o = 0; o < 3; o++) {
            float s = __ldg(b2 + o);
#pragma unroll
            for (int j = 0; j < 10; j++) s += h[j] * __ldg(w2 + o * 10 + j);
            y[o] = s;
        }
        float mu = (y[0] + y[1] + y[2]) * (1.0f / 3.0f);
        float d0 = y[0] - mu, d1 = y[1] - mu, d2 = y[2] - mu;
        float var = (d0 * d0 + d1 * d1 + d2 * d2) * (1.0f / 3.0f);
        float rs = rsqrtf(var + 1e-5f);
        sv[MEM_DIM + 3 * tid + 0] = d0 * rs * __ldg(lg + 0) + __ldg(lb + 0);
        sv[MEM_DIM + 3 * tid + 1] = d1 * rs * __ldg(lg + 1) + __ldg(lb + 1);
        sv[MEM_DIM + 3 * tid + 2] = d2 * rs * __ldg(lg + 2) + __ldg(lb + 2);
    }
    __syncthreads();

    float s1 = 0.0f, s2 = 0.0f;
    for (int k = tid; k < D_MSG; k += 64) { float v = sv[k]; s1 += v; s2 += v * v; }
#pragma unroll
    for (int o = 16; o > 0; o >>= 1) {
        s1 += __shfl_down_sync(0xFFFFFFFFu, s1, o);
        s2 += __shfl_down_sync(0xFFFFFFFFu, s2, o);
    }
    if ((tid & 31) == 0) { red[tid >> 5] = s1; red[2 + (tid >> 5)] = s2; }
    __syncthreads();
    if (tid == 0) {
        float t1 = red[0] + red[1];
        float t2 = red[2] + red[3];
        float mu = t1 * (1.0f / 292.0f);
        float var = t2 * (1.0f / 292.0f) - mu * mu;
        s_mu = mu;
        s_rs = rsqrtf(var + 1e-5f);
    }
    __syncthreads();

    float mu = s_mu, rs = s_rs;
    for (int k = tid; k < D_MSG; k += 64) {
        float v = (sv[k] - mu) * rs * __ldg(lng + k) + __ldg(lnb + k);
        g_A[base + k] = __float2half_rn(v);
    }
    for (int c = tid; c < MEM_DIM; c += 64) {
        float v = sv[c];
        g_A[base + D_MSG + c] = __float2half_rn(v);
        g_mem[(size_t)i * MEM_DIM + c] = v;
    }
    if (tid < 24) g_A[base + KREAL + tid] = __float2half_rn(0.0f);
}

// ---------------------------------------------------------------------------
// Kernel 2: fp16 HMMA GEMM + register-fused GRU epilogue. K=416, one term.
// BM=128 BN=80 BK=32, 256 threads, 8 warps (4x2, warp tile 32x40).
// 3-stage cp.async pipeline (wait_group 1).
// ---------------------------------------------------------------------------
#define BM 128
#define BN 80
#define BK 32
#define LDS 40
#define NKT (KTOT / BK)   // 13
#define A_H (BM * LDS)    // 5120 halves
#define B_H (BN * LDS)    // 3200 halves
#define STG_H (A_H + B_H) // 8320 halves = 16640 B
#define SMEM_GEMM (3 * STG_H * 2)   // 49920 B

__global__ __launch_bounds__(256, 2) void gemm11(float* __restrict__ out, int N) {
    extern __shared__ __align__(16) uint16_t smx[];

    int tid = threadIdx.x;
    int lane = tid & 31, wid = tid >> 5;
    int wm = wid & 3, wn = wid >> 2;            // 4 x 2 warp grid
    int row0 = blockIdx.y * BM;
    int colblk = blockIdx.x;                    // channels [colblk*20, +20)
    int col0 = colblk * BN;

    const uint16_t* gA = (const uint16_t*)g_A;
    const uint16_t* gB = (const uint16_t*)g_B;

    float acc[2][5][4];
#pragma unroll
    for (int mf = 0; mf < 2; mf++)
#pragma unroll
        for (int nf = 0; nf < 5; nf++)
#pragma unroll
            for (int q = 0; q < 4; q++) acc[mf][nf][q] = 0.0f;

    // ---- hoisted loader geometry: up to 4 chunks/thread (A:512, B:320) ----
    const uint16_t* gsrc[4];
    uint32_t sdst[4];
    bool valid[4];
#pragma unroll
    for (int q = 0; q < 4; q++) {
        int id = tid + q * 256;
        valid[q] = (id < 832);
        if (id < 512) {
            int r = id >> 2, c = id & 3;
            gsrc[q] = gA + (size_t)(row0 + r) * AK + c * 8;
            sdst[q] = r * LDS + c * 8;
        } else if (id < 832) {
            int id2 = id - 512;
            int r = id2 >> 2, c = id2 & 3;
            gsrc[q] = gB + (size_t)(col0 + r) * KTOT + c * 8;
            sdst[q] = A_H + r * LDS + c * 8;
        } else {
            gsrc[q] = gB; sdst[q] = 0;
        }
    }
    uint32_t sbase = smem_u32(smx);

    auto load_stage = [&](int stage, int k0) {
        uint32_t soff = sbase + (uint32_t)(stage * STG_H) * 2;
#pragma unroll
        for (int q = 0; q < 4; q++) {
            if (!valid[q]) continue;
            cp_async16(soff + sdst[q] * 2, gsrc[q] + k0);
        }
        cp_commit();
    };

    load_stage(0, 0);
    load_stage(1, BK);

    for (int kt = 0; kt < NKT; kt++) {
        int buf = kt % 3;
        cp_wait1();
        __syncthreads();
        if (kt + 2 < NKT) load_stage((kt + 2) % 3, (kt + 2) * BK);

        uint16_t* As = smx + buf * STG_H;
        uint16_t* Bs = As + A_H;
#pragma unroll
        for (int ks = 0; ks < 2; ks++) {
            int k0 = ks * 16;
            uint32_t a[2][4], b[5][2];
#pragma unroll
            for (int mf = 0; mf < 2; mf++) {
                int r = wm * 32 + mf * 16 + (lane & 15);
                int c = k0 + (lane >> 4) * 8;
                ldmx4(a[mf], smem_u32(&As[r * LDS + c]));
            }
#pragma unroll
            for (int pr = 0; pr < 2; pr++) {
                int r = wn * 40 + pr * 16 + (lane & 7) + ((lane >> 4) << 3);
                int c = k0 + ((lane >> 3) & 1) * 8;
                uint32_t bb[4];
                ldmx4(bb, smem_u32(&Bs[r * LDS + c]));
                b[2 * pr][0] = bb[0]; b[2 * pr][1] = bb[1];
                b[2 * pr + 1][0] = bb[2]; b[2 * pr + 1][1] = bb[3];
            }
            {   // last n-frag via x2
                int r = wn * 40 + 32 + (lane & 7);
                int c = k0 + ((lane >> 3) & 1) * 8;
                ldmx2(b[4], smem_u32(&Bs[r * LDS + c]));
            }
#pragma unroll
            for (int mf = 0; mf < 2; mf++)
#pragma unroll
                for (int nf = 0; nf < 5; nf++)
                    mma16816(acc[mf][nf], a[mf], b[nf]);
        }
    }

    // Register-fused GRU epilogue.
#pragma unroll
    for (int mf = 0; mf < 2; mf++) {
        int r0i = row0 + wm * 32 + mf * 16 + (lane >> 2);
#pragma unroll
        for (int nf = 0; nf < 5; nf++) {
            float n0 = __shfl_xor_sync(0xFFFFFFFFu, acc[mf][nf][0], 1);
            float n1 = __shfl_xor_sync(0xFFFFFFFFu, acc[mf][nf][1], 1);
            float n2 = __shfl_xor_sync(0xFFFFFFFFu, acc[mf][nf][2], 1);
            float n3 = __shfl_xor_sync(0xFFFFFFFFu, acc[mf][nf][3], 1);
            if (!(lane & 1)) {
                int ch = colblk * 20 + wn * 10 + nf * 2 + ((lane & 3) >> 1);
                if (ch < MEM_DIM) {
                    if (r0i < N) {
                        float rr = 1.0f / (1.0f + expf(-acc[mf][nf][0]));
                        float zz = 1.0f / (1.0f + expf(-acc[mf][nf][1]));
                        float nn = tanhf(fmaf(rr, n1, n0));
                        float m = g_mem[(size_t)r0i * MEM_DIM + ch];
                        out[(size_t)r0i * MEM_DIM + ch] = (1.0f - zz) * nn + zz * m;
                    }
                    int r1i = r0i + 8;
                    if (r1i < N) {
                        float rr = 1.0f / (1.0f + expf(-acc[mf][nf][2]));
                        float zz = 1.0f / (1.0f + expf(-acc[mf][nf][3]));
                        float nn = tanhf(fmaf(rr, n3, n2));
                        float m = g_mem[(size_t)r1i * MEM_DIM + ch];
                        out[(size_t)r1i * MEM_DIM + ch] = (1.0f - zz) * nn + zz * m;
                    }
                }
            }
        }
    }
}

// ---------------------------------------------------------------------------
extern "C" void kernel_launch(void* const* d_in, const int* in_sizes, int n_in,
                              void* d_out, int out_size) {
    const int*   n_id   = (const int*)d_in[0];
    const float* memory = (const float*)d_in[1];
    const float* msgs   = (const float*)d_in[2];
    const float* w1     = (const float*)d_in[3];
    const float* b1     = (const float*)d_in[4];
    const float* w2     = (const float*)d_in[5];
    const float* b2     = (const float*)d_in[6];
    const float* lg     = (const float*)d_in[7];
    const float* lb     = (const float*)d_in[8];
    const float* lng    = (const float*)d_in[9];
    const float* lnb    = (const float*)d_in[10];
    const float* wih    = (const float*)d_in[11];
    const float* whh    = (const float*)d_in[12];
    float* out = (float*)d_out;

    int N = in_sizes[0];
    if (N > N_MAXN) N = N_MAXN;

    cudaFuncSetAttribute(gemm11, cudaFuncAttributeMaxDynamicSharedMemorySize, SMEM_GEMM);

    buildB<<<(JB * KTOT + 255) / 256, 256>>>(wih, whh);
    phase1<<<NPAD, 64>>>(n_id, memory, msgs, w1, b1, w2, b2, lg, lb, lng, lnb, N);
    dim3 grid(5, NPAD / BM);   // col-block fast -> A shared in L2
    gemm11<<<grid, 256, SMEM_GEMM>>>(out, N);
}

// round 12
// speedup vs baseline: 2.2281x; 1.2526x over previous
#include <cuda_runtime.h>
#include <cuda_fp16.h>
#include <math.h>
#include <stdint.h>

// ---------------- problem constants ----------------
#define N_MAXN    50000
#define NPAD      50048          // 391*128, also 6256*8
#define MEM_DIM   100
#define RAW       64
#define TIN       20
#define D_MSG     292
#define KREAL     392            // 292 x + 100 mem
#define AK        416            // K padded to 13*32
#define KTOT      416
#define JB        400            // B rows: j = channel*4 + group, channel<100

// ---------------- scratch ----------------
__device__ __half g_A[(size_t)NPAD * AK];    // ~42 MB
__device__ __half g_B[(size_t)JB * KTOT];    // ~0.33 MB
__device__ float  g_mem[(size_t)NPAD * MEM_DIM];

__device__ __forceinline__ uint32_t smem_u32(const void* p) {
    uint32_t a;
    asm("{ .reg .u64 t; cvta.to.shared.u64 t, %1; cvt.u32.u64 %0, t; }" : "=r"(a) : "l"(p));
    return a;
}
__device__ __forceinline__ void cp_async16(uint32_t dst, const void* src) {
    asm volatile("cp.async.cg.shared.global [%0], [%1], 16;" :: "r"(dst), "l"(src));
}
__device__ __forceinline__ void cp_commit() {
    asm volatile("cp.async.commit_group;" ::: "memory");
}
__device__ __forceinline__ void cp_wait1() {
    asm volatile("cp.async.wait_group 1;" ::: "memory");
}
__device__ __forceinline__ void ldmx4(uint32_t* r, uint32_t addr) {
    asm volatile("ldmatrix.sync.aligned.m8n8.x4.shared.b16 {%0,%1,%2,%3}, [%4];"
        : "=r"(r[0]), "=r"(r[1]), "=r"(r[2]), "=r"(r[3]) : "r"(addr));
}
__device__ __forceinline__ void ldmx2(uint32_t* r, uint32_t addr) {
    asm volatile("ldmatrix.sync.aligned.m8n8.x2.shared.b16 {%0,%1}, [%2];"
        : "=r"(r[0]), "=r"(r[1]) : "r"(addr));
}
__device__ __forceinline__ void mma16816(float* d, const uint32_t* a, const uint32_t* b) {
    asm volatile(
        "mma.sync.aligned.m16n8k16.row.col.f32.f16.f16.f32 "
        "{%0,%1,%2,%3}, {%4,%5,%6,%7}, {%8,%9}, {%0,%1,%2,%3};"
        : "+f"(d[0]), "+f"(d[1]), "+f"(d[2]), "+f"(d[3])
        : "r"(a[0]), "r"(a[1]), "r"(a[2]), "r"(a[3]), "r"(b[0]), "r"(b[1]));
}

// ---------------------------------------------------------------------------
// Kernel 0: pack GRU weights -> g_B [400][416] fp16.
// ---------------------------------------------------------------------------
__global__ void buildB(const float* __restrict__ wih, const float* __restrict__ whh) {
    int idx = blockIdx.x * blockDim.x + threadIdx.x;
    if (idx >= JB * KTOT) return;
    int j = idx / KTOT, k = idx % KTOT;
    int c = j >> 2, g = j & 3;
    float v = 0.0f;
    if (k < D_MSG) {
        if (g == 0) v = wih[c * D_MSG + k];
        else if (g == 1) v = wih[(100 + c) * D_MSG + k];
        else if (g == 2) v = wih[(200 + c) * D_MSG + k];
    } else if (k < KREAL) {
        int m = k - D_MSG;
        if (g == 0) v = whh[c * MEM_DIM + m];
        else if (g == 1) v = whh[(100 + c) * MEM_DIM + m];
        else if (g == 3) v = whh[(200 + c) * MEM_DIM + m];
    }
    g_B[idx] = __float2half_rn(v);
}

// ---------------------------------------------------------------------------
// Kernel 1: warp-per-node msg MLP + layernorms -> g_A fp16[416] + g_mem.
// 256 threads = 8 warps = 8 nodes per block. Each lane owns 2 msg rows.
// ---------------------------------------------------------------------------
__global__ __launch_bounds__(256) void phase1(
    const int* __restrict__ n_id,
    const float* __restrict__ memory,
    const float* __restrict__ msgs,
    const float* __restrict__ w1, const float* __restrict__ b1,
    const float* __restrict__ w2, const float* __restrict__ b2,
    const float* __restrict__ lg, const float* __restrict__ lb,
    const float* __restrict__ lng, const float* __restrict__ lnb,
    int N)
{
    __shared__ float w1s[200], w2s[30];
    __shared__ float b1s[10], b2s[3], lgs[3], lbs[3];
    __shared__ float sv[8][296];             // per-warp [mem(100)|comp(192)]

    int tid = threadIdx.x;
    int warp = tid >> 5, lane = tid & 31;

    // one-time per-block weight staging
    if (tid < 200) w1s[tid] = w1[tid];
    else if (tid < 230) w2s[tid - 200] = w2[tid - 200];
    else if (tid < 240) b1s[tid - 230] = b1[tid - 230];
    else if (tid < 243) b2s[tid - 240] = b2[tid - 240];
    else if (tid < 246) lgs[tid - 243] = lg[tid - 243];
    else if (tid < 249) lbs[tid - 246] = lb[tid - 246];
    __syncthreads();

    int i = blockIdx.x * 8 + warp;
    size_t base = (size_t)i * AK;

    if (i >= N) {  // zero pad row: 416 halves = 52 uint4
        uint4 z = make_uint4(0, 0, 0, 0);
        uint4* dst = (uint4*)(g_A + base);
        if (lane < 26) { dst[lane] = z; dst[lane + 26] = z; }
        return;
    }
    int row = n_id[i];
    float* svw = sv[warp];

    // memory row -> smem
    const float* memrow = memory + (size_t)row * MEM_DIM;
#pragma unroll
    for (int c = lane; c < MEM_DIM; c += 32) svw[c] = memrow[c];

    // load this lane's 2 msg rows straight into registers
    float mr[2][TIN];
    const float4* m4 = (const float4*)(msgs + (size_t)row * (RAW * TIN));
#pragma unroll
    for (int rr = 0; rr < 2; rr++) {
        int r = 2 * lane + rr;
#pragma unroll
        for (int q = 0; q < 5; q++) {
            float4 v = __ldg(m4 + r * 5 + q);
            mr[rr][q * 4 + 0] = v.x; mr[rr][q * 4 + 1] = v.y;
            mr[rr][q * 4 + 2] = v.z; mr[rr][q * 4 + 3] = v.w;
        }
    }

    // MLP: both rows share each weight load
    float h0[10], h1[10];
#pragma unroll
    for (int j = 0; j < 10; j++) {
        float s0 = b1s[j], s1 = b1s[j];
#pragma unroll
        for (int t = 0; t < TIN; t++) {
            float w = w1s[j * TIN + t];
            s0 = fmaf(mr[0][t], w, s0);
            s1 = fmaf(mr[1][t], w, s1);
        }
        h0[j] = 0.5f * s0 * (1.0f + erff(s0 * 0.7071067811865476f));
        h1[j] = 0.5f * s1 * (1.0f + erff(s1 * 0.7071067811865476f));
    }
#pragma unroll
    for (int rr = 0; rr < 2; rr++) {
        const float* h = rr ? h1 : h0;
        float y[3];
#pragma unroll
        for (int o = 0; o < 3; o++) {
            float s = b2s[o];
#pragma unroll
            for (int j = 0; j < 10; j++) s = fmaf(h[j], w2s[o * 10 + j], s);
            y[o] = s;
        }
        float mu = (y[0] + y[1] + y[2]) * (1.0f / 3.0f);
        float d0 = y[0] - mu, d1 = y[1] - mu, d2 = y[2] - mu;
        float var = (d0 * d0 + d1 * d1 + d2 * d2) * (1.0f / 3.0f);
        float rs = rsqrtf(var + 1e-5f);
        int r = 2 * lane + rr;
        svw[MEM_DIM + 3 * r + 0] = d0 * rs * lgs[0] + lbs[0];
        svw[MEM_DIM + 3 * r + 1] = d1 * rs * lgs[1] + lbs[1];
        svw[MEM_DIM + 3 * r + 2] = d2 * rs * lgs[2] + lbs[2];
    }
    __syncwarp();

    // LayerNorm over 292 — warp-local, all lanes get the result
    float s1 = 0.0f, s2 = 0.0f;
#pragma unroll
    for (int k = lane; k < D_MSG; k += 32) { float v = svw[k]; s1 += v; s2 += v * v; }
#pragma unroll
    for (int o = 16; o > 0; o >>= 1) {
        s1 += __shfl_xor_sync(0xFFFFFFFFu, s1, o);
        s2 += __shfl_xor_sync(0xFFFFFFFFu, s2, o);
    }
    float mu = s1 * (1.0f / 292.0f);
    float var = s2 * (1.0f / 292.0f) - mu * mu;
    float rs = rsqrtf(var + 1e-5f);

#pragma unroll
    for (int k = lane; k < D_MSG; k += 32) {
        float v = (svw[k] - mu) * rs * __ldg(lng + k) + __ldg(lnb + k);
        g_A[base + k] = __float2half_rn(v);
    }
#pragma unroll
    for (int c = lane; c < MEM_DIM; c += 32) {
        float v = svw[c];
        g_A[base + D_MSG + c] = __float2half_rn(v);
        g_mem[(size_t)i * MEM_DIM + c] = v;
    }
    if (lane < 24) g_A[base + KREAL + lane] = __float2half_rn(0.0f);
}

// ---------------------------------------------------------------------------
// Kernel 2: fp16 HMMA GEMM + register-fused GRU epilogue. K=416 (unchanged).
// ---------------------------------------------------------------------------
#define BM 128
#define BN 80
#define BK 32
#define LDS 40
#define NKT (KTOT / BK)   // 13
#define A_H (BM * LDS)    // 5120 halves
#define B_H (BN * LDS)    // 3200 halves
#define STG_H (A_H + B_H) // 8320 halves
#define SMEM_GEMM (3 * STG_H * 2)   // 49920 B

__global__ __launch_bounds__(256, 2) void gemm12(float* __restrict__ out, int N) {
    extern __shared__ __align__(16) uint16_t smx[];

    int tid = threadIdx.x;
    int lane = tid & 31, wid = tid >> 5;
    int wm = wid & 3, wn = wid >> 2;            // 4 x 2 warp grid
    int row0 = blockIdx.y * BM;
    int colblk = blockIdx.x;                    // channels [colblk*20, +20)
    int col0 = colblk * BN;

    const uint16_t* gA = (const uint16_t*)g_A;
    const uint16_t* gB = (const uint16_t*)g_B;

    float acc[2][5][4];
#pragma unroll
    for (int mf = 0; mf < 2; mf++)
#pragma unroll
        for (int nf = 0; nf < 5; nf++)
#pragma unroll
            for (int q = 0; q < 4; q++) acc[mf][nf][q] = 0.0f;

    const uint16_t* gsrc[4];
    uint32_t sdst[4];
    bool valid[4];
#pragma unroll
    for (int q = 0; q < 4; q++) {
        int id = tid + q * 256;
        valid[q] = (id < 832);
        if (id < 512) {
            int r = id >> 2, c = id & 3;
            gsrc[q] = gA + (size_t)(row0 + r) * AK + c * 8;
            sdst[q] = r * LDS + c * 8;
        } else if (id < 832) {
            int id2 = id - 512;
            int r = id2 >> 2, c = id2 & 3;
            gsrc[q] = gB + (size_t)(col0 + r) * KTOT + c * 8;
            sdst[q] = A_H + r * LDS + c * 8;
        } else {
            gsrc[q] = gB; sdst[q] = 0;
        }
    }
    uint32_t sbase = smem_u32(smx);

    auto load_stage = [&](int stage, int k0) {
        uint32_t soff = sbase + (uint32_t)(stage * STG_H) * 2;
#pragma unroll
        for (int q = 0; q < 4; q++) {
            if (!valid[q]) continue;
            cp_async16(soff + sdst[q] * 2, gsrc[q] + k0);
        }
        cp_commit();
    };

    load_stage(0, 0);
    load_stage(1, BK);

    for (int kt = 0; kt < NKT; kt++) {
        int buf = kt % 3;
        cp_wait1();
        __syncthreads();
        if (kt + 2 < NKT) load_stage((kt + 2) % 3, (kt + 2) * BK);

        uint16_t* As = smx + buf * STG_H;
        uint16_t* Bs = As + A_H;
#pragma unroll
        for (int ks = 0; ks < 2; ks++) {
            int k0 = ks * 16;
            uint32_t a[2][4], b[5][2];
#pragma unroll
            for (int mf = 0; mf < 2; mf++) {
                int r = wm * 32 + mf * 16 + (lane & 15);
                int c = k0 + (lane >> 4) * 8;
                ldmx4(a[mf], smem_u32(&As[r * LDS + c]));
            }
#pragma unroll
            for (int pr = 0; pr < 2; pr++) {
                int r = wn * 40 + pr * 16 + (lane & 7) + ((lane >> 4) << 3);
                int c = k0 + ((lane >> 3) & 1) * 8;
                uint32_t bb[4];
                ldmx4(bb, smem_u32(&Bs[r * LDS + c]));
                b[2 * pr][0] = bb[0]; b[2 * pr][1] = bb[1];
                b[2 * pr + 1][0] = bb[2]; b[2 * pr + 1][1] = bb[3];
            }
            {
                int r = wn * 40 + 32 + (lane & 7);
                int c = k0 + ((lane >> 3) & 1) * 8;
                ldmx2(b[4], smem_u32(&Bs[r * LDS + c]));
            }
#pragma unroll
            for (int mf = 0; mf < 2; mf++)
#pragma unroll
                for (int nf = 0; nf < 5; nf++)
                    mma16816(acc[mf][nf], a[mf], b[nf]);
        }
    }

    // Register-fused GRU epilogue.
#pragma unroll
    for (int mf = 0; mf < 2; mf++) {
        int r0i = row0 + wm * 32 + mf * 16 + (lane >> 2);
#pragma unroll
        for (int nf = 0; nf < 5; nf++) {
            float n0 = __shfl_xor_sync(0xFFFFFFFFu, acc[mf][nf][0], 1);
            float n1 = __shfl_xor_sync(0xFFFFFFFFu, acc[mf][nf][1], 1);
            float n2 = __shfl_xor_sync(0xFFFFFFFFu, acc[mf][nf][2], 1);
            float n3 = __shfl_xor_sync(0xFFFFFFFFu, acc[mf][nf][3], 1);
            if (!(lane & 1)) {
                int ch = colblk * 20 + wn * 10 + nf * 2 + ((lane & 3) >> 1);
                if (ch < MEM_DIM) {
                    if (r0i < N) {
                        float rr = 1.0f / (1.0f + expf(-acc[mf][nf][0]));
                        float zz = 1.0f / (1.0f + expf(-acc[mf][nf][1]));
                        float nn = tanhf(fmaf(rr, n1, n0));
                        float m = g_mem[(size_t)r0i * MEM_DIM + ch];
                        out[(size_t)r0i * MEM_DIM + ch] = (1.0f - zz) * nn + zz * m;
                    }
                    int r1i = r0i + 8;
                    if (r1i < N) {
                        float rr = 1.0f / (1.0f + expf(-acc[mf][nf][2]));
                        float zz = 1.0f / (1.0f + expf(-acc[mf][nf][3]));
                        float nn = tanhf(fmaf(rr, n3, n2));
                        float m = g_mem[(size_t)r1i * MEM_DIM + ch];
                        out[(size_t)r1i * MEM_DIM + ch] = (1.0f - zz) * nn + zz * m;
                    }
                }
            }
        }
    }
}

// ---------------------------------------------------------------------------
extern "C" void kernel_launch(void* const* d_in, const int* in_sizes, int n_in,
                              void* d_out, int out_size) {
    const int*   n_id   = (const int*)d_in[0];
    const float* memory = (const float*)d_in[1];
    const float* msgs   = (const float*)d_in[2];
    const float* w1     = (const float*)d_in[3];
    const float* b1     = (const float*)d_in[4];
    const float* w2     = (const float*)d_in[5];
    const float* b2     = (const float*)d_in[6];
    const float* lg     = (const float*)d_in[7];
    const float* lb     = (const float*)d_in[8];
    const float* lng    = (const float*)d_in[9];
    const float* lnb    = (const float*)d_in[10];
    const float* wih    = (const float*)d_in[11];
    const float* whh    = (const float*)d_in[12];
    float* out = (float*)d_out;

    int N = in_sizes[0];
    if (N > N_MAXN) N = N_MAXN;

    cudaFuncSetAttribute(gemm12, cudaFuncAttributeMaxDynamicSharedMemorySize, SMEM_GEMM);

    buildB<<<(JB * KTOT + 255) / 256, 256>>>(wih, whh);
    phase1<<<NPAD / 8, 256>>>(n_id, memory, msgs, w1, b1, w2, b2, lg, lb, lng, lnb, N);
    dim3 grid(5, NPAD / BM);   // col-block fast -> A shared in L2
    gemm12<<<grid, 256, SMEM_GEMM>>>(out, N);
}